// round 4
// baseline (speedup 1.0000x reference)
#include <cuda_runtime.h>
#include <cuda_bf16.h>
#include <cstdio>

// Problem constants
#define N0 100000
#define N1 25000
#define N2 6250
#define E0 1600000
#define E1 400000
#define E2 100000
#define NF 128
#define NH 128
#define NC 40

// ---------------------------------------------------------------------------
// Scratch (device globals — no allocation allowed)
// ---------------------------------------------------------------------------
__device__ __align__(16) float g_xW[(size_t)N0 * NH];     // x @ gc1_W
__device__ __align__(16) float g_p1[(size_t)N1 * NH];
__device__ __align__(16) float g_q1[(size_t)N1 * NH];
__device__ __align__(16) float g_k1[(size_t)N1 * NH];
__device__ __align__(16) float g_h01[(size_t)N1 * NH];
__device__ __align__(16) float g_msg1[(size_t)N1 * NH];
__device__ __align__(16) float g_c1[(size_t)N1 * NH];
__device__ __align__(16) float g_p2[(size_t)N2 * NH];
__device__ __align__(16) float g_q2[(size_t)N2 * NH];
__device__ __align__(16) float g_k2[(size_t)N2 * NH];
__device__ __align__(16) float g_h02[(size_t)N2 * NH];
__device__ __align__(16) float g_msg2[(size_t)N2 * NH];
__device__ __align__(16) float g_c2[(size_t)N2 * NH];
__device__ __align__(16) float g_hW2[(size_t)N0 * NC];
__device__ float g_logit1[E1];
__device__ float g_z1[N1];
__device__ unsigned g_max1[N1];
__device__ float g_logit2[E2];
__device__ float g_z2[N2];
__device__ unsigned g_max2[N2];
// CSR scratch for A0 (dst-sorted)
__device__ int   g_cnt[N0];          // histogram / cursor
__device__ int   g_rowptr[N0 + 1];
__device__ int   g_bsum[128];
__device__ int   g_esrc[E0];
__device__ float g_eval[E0];

// ---------------------------------------------------------------------------
// Helpers
// ---------------------------------------------------------------------------
__device__ __forceinline__ unsigned f2ord(float f) {
    unsigned u = __float_as_uint(f);
    return (u & 0x80000000u) ? ~u : (u | 0x80000000u);
}
__device__ __forceinline__ float ord2f(unsigned u) {
    return __uint_as_float((u & 0x80000000u) ? (u & 0x7FFFFFFFu) : ~u);
}
__device__ __forceinline__ void red_add_v4(float4* addr, float a, float b, float c, float d) {
    asm volatile("red.global.add.v4.f32 [%0], {%1, %2, %3, %4};"
                 :: "l"(addr), "f"(a), "f"(b), "f"(c), "f"(d) : "memory");
}

// ---------------------------------------------------------------------------
// CSR build kernels
// ---------------------------------------------------------------------------
__global__ void hist_k(const int* __restrict__ dsts, int* __restrict__ cnt, int E) {
    int e = blockIdx.x * blockDim.x + threadIdx.x;
    if (e < E) atomicAdd(cnt + dsts[e], 1);
}
// Phase A: per-block inclusive scan of 1024 elems (256 thr x 4), write rowptr[i+1]
__global__ void scan1_k(const int* __restrict__ cnt, int* __restrict__ rowptr,
                        int* __restrict__ bsum, int n) {
    __shared__ int s[256];
    int t = threadIdx.x;
    int base = blockIdx.x * 1024 + t * 4;
    int v0 = (base + 0 < n) ? cnt[base + 0] : 0;
    int v1 = (base + 1 < n) ? cnt[base + 1] : 0;
    int v2 = (base + 2 < n) ? cnt[base + 2] : 0;
    int v3 = (base + 3 < n) ? cnt[base + 3] : 0;
    int x0 = v0, x1 = x0 + v1, x2 = x1 + v2, x3 = x2 + v3;
    s[t] = x3;
    __syncthreads();
    for (int off = 1; off < 256; off <<= 1) {
        int val = 0;
        if (t >= off) val = s[t - off];
        __syncthreads();
        if (t >= off) s[t] += val;
        __syncthreads();
    }
    int prev = (t > 0) ? s[t - 1] : 0;
    if (base + 0 < n) rowptr[base + 1] = prev + x0;
    if (base + 1 < n) rowptr[base + 2] = prev + x1;
    if (base + 2 < n) rowptr[base + 3] = prev + x2;
    if (base + 3 < n) rowptr[base + 4] = prev + x3;
    if (t == 255) bsum[blockIdx.x] = s[255];
}
// Phase B: serial exclusive scan of block sums (tiny)
__global__ void scan2_k(int* __restrict__ bsum, int nb) {
    if (threadIdx.x == 0) {
        int run = 0;
        for (int i = 0; i < nb; i++) { int v = bsum[i]; bsum[i] = run; run += v; }
    }
}
// Phase C: add block offsets
__global__ void scan3_k(int* __restrict__ rowptr, const int* __restrict__ bsum, int n) {
    int i = blockIdx.x * blockDim.x + threadIdx.x;
    if (i == 0) rowptr[0] = 0;
    if (i < n) rowptr[i + 1] += bsum[i >> 10];
}
__global__ void scatter_edges_k(const int* __restrict__ dsts, const int* __restrict__ srcs,
                                const float* __restrict__ val, const int* __restrict__ rowptr,
                                int* __restrict__ cur, int* __restrict__ esrc,
                                float* __restrict__ eval, int E) {
    int e = blockIdx.x * blockDim.x + threadIdx.x;
    if (e >= E) return;
    int d = dsts[e];
    int pos = rowptr[d] + atomicAdd(cur + d, 1);
    esrc[pos] = srcs[e];
    eval[pos] = val[e];
}

// ---------------------------------------------------------------------------
// CSR SpMM (128 feats) fused: gcn = relu(A0 @ xW + b); p1[assign0] += gcn
// One warp per dst row; 4 floats per lane in registers.
// ---------------------------------------------------------------------------
__global__ __launch_bounds__(256)
void spmm_csr128_fused(const int* __restrict__ rowptr, const int* __restrict__ esrc,
                       const float* __restrict__ eval, const float* __restrict__ X,
                       const float* __restrict__ bias, float* __restrict__ gcn,
                       const int* __restrict__ assign0, float* __restrict__ p1) {
    int w = (blockIdx.x * blockDim.x + threadIdx.x) >> 5;
    int lane = threadIdx.x & 31;
    if (w >= N0) return;
    int s = rowptr[w], e = rowptr[w + 1];
    float4 acc = ((const float4*)bias)[lane];
    int i = s;
#pragma unroll 1
    for (; i + 1 < e; i += 2) {
        int s0 = esrc[i], s1 = esrc[i + 1];
        float v0 = eval[i], v1 = eval[i + 1];
        float4 a0 = ((const float4*)(X + (size_t)s0 * NH))[lane];
        float4 a1 = ((const float4*)(X + (size_t)s1 * NH))[lane];
        acc.x += v0 * a0.x + v1 * a1.x;
        acc.y += v0 * a0.y + v1 * a1.y;
        acc.z += v0 * a0.z + v1 * a1.z;
        acc.w += v0 * a0.w + v1 * a1.w;
    }
    if (i < e) {
        int s0 = esrc[i]; float v0 = eval[i];
        float4 a0 = ((const float4*)(X + (size_t)s0 * NH))[lane];
        acc.x += v0 * a0.x; acc.y += v0 * a0.y;
        acc.z += v0 * a0.z; acc.w += v0 * a0.w;
    }
    acc.x = fmaxf(acc.x, 0.f); acc.y = fmaxf(acc.y, 0.f);
    acc.z = fmaxf(acc.z, 0.f); acc.w = fmaxf(acc.w, 0.f);
    ((float4*)(gcn + (size_t)w * NH))[lane] = acc;
    int d = assign0[w];
    red_add_v4(((float4*)(p1 + (size_t)d * NH)) + lane, acc.x, acc.y, acc.z, acc.w);
}

// ---------------------------------------------------------------------------
// CSR SpMM (40 feats) fused bias: out = A0 @ hW2 + b2.  Lanes 0..9 hold float4.
// ---------------------------------------------------------------------------
__global__ __launch_bounds__(256)
void spmm_csr40(const int* __restrict__ rowptr, const int* __restrict__ esrc,
                const float* __restrict__ eval, const float* __restrict__ X,
                const float* __restrict__ bias, float* __restrict__ out) {
    int w = (blockIdx.x * blockDim.x + threadIdx.x) >> 5;
    int lane = threadIdx.x & 31;
    if (w >= N0) return;
    int s = rowptr[w], e = rowptr[w + 1];
    bool act = lane < 10;
    float4 acc = act ? ((const float4*)bias)[lane] : make_float4(0, 0, 0, 0);
    for (int i = s; i < e; i++) {
        int s0 = esrc[i]; float v0 = eval[i];
        if (act) {
            float4 a = ((const float4*)(X + (size_t)s0 * NC))[lane];
            acc.x += v0 * a.x; acc.y += v0 * a.y;
            acc.z += v0 * a.z; acc.w += v0 * a.w;
        }
    }
    if (act) ((float4*)(out + (size_t)w * NC))[lane] = acc;
}

// ---------------------------------------------------------------------------
// High-throughput SGEMM specialized for N = K = 128 (dual-output launch).
// ---------------------------------------------------------------------------
#define BM 128
#define BN 128
#define BKK 16
__global__ __launch_bounds__(256, 2)
void gemm_nk128(const float* __restrict__ A,
                const float* __restrict__ Ba, const float* __restrict__ Bb,
                float* __restrict__ Ca, float* __restrict__ Cb, int M) {
    __shared__ float As[BKK][BM + 4];
    __shared__ float Bs[BKK][BN];
    const float* __restrict__ B = (blockIdx.x == 0) ? Ba : Bb;
    float* __restrict__ C = (blockIdx.x == 0) ? Ca : Cb;

    int tid = threadIdx.x;
    int row0 = blockIdx.y * BM;
    int trow = tid >> 4;
    int tcol = tid & 15;

    float acc[8][8] = {};
    float a_reg[8], b_reg[8];

    for (int k0 = 0; k0 < 128; k0 += BKK) {
#pragma unroll
        for (int i = 0; i < 2; i++) {
            int idx = tid + i * 256;
            int r = idx >> 2;
            int kq = idx & 3;
            float4 v = make_float4(0.f, 0.f, 0.f, 0.f);
            int gr = row0 + r;
            if (gr < M)
                v = *(const float4*)(A + (size_t)gr * 128 + k0 + kq * 4);
            As[kq * 4 + 0][r] = v.x;
            As[kq * 4 + 1][r] = v.y;
            As[kq * 4 + 2][r] = v.z;
            As[kq * 4 + 3][r] = v.w;
        }
#pragma unroll
        for (int i = 0; i < 2; i++) {
            int idx = tid + i * 256;
            int r = idx >> 5;
            int c4 = idx & 31;
            float4 v = *(const float4*)(B + (size_t)(k0 + r) * 128 + c4 * 4);
            *(float4*)(&Bs[r][c4 * 4]) = v;
        }
        __syncthreads();
#pragma unroll
        for (int kk = 0; kk < BKK; kk++) {
            *(float4*)(a_reg)     = *(const float4*)(&As[kk][trow * 8]);
            *(float4*)(a_reg + 4) = *(const float4*)(&As[kk][trow * 8 + 4]);
            *(float4*)(b_reg)     = *(const float4*)(&Bs[kk][tcol * 8]);
            *(float4*)(b_reg + 4) = *(const float4*)(&Bs[kk][tcol * 8 + 4]);
#pragma unroll
            for (int i = 0; i < 8; i++)
#pragma unroll
                for (int j = 0; j < 8; j++)
                    acc[i][j] += a_reg[i] * b_reg[j];
        }
        __syncthreads();
    }
#pragma unroll
    for (int i = 0; i < 8; i++) {
        int gr = row0 + trow * 8 + i;
        if (gr >= M) continue;
        float* cp = C + (size_t)gr * 128 + tcol * 8;
        *(float4*)(cp)     = make_float4(acc[i][0], acc[i][1], acc[i][2], acc[i][3]);
        *(float4*)(cp + 4) = make_float4(acc[i][4], acc[i][5], acc[i][6], acc[i][7]);
    }
}

// ---------------------------------------------------------------------------
// GEMM for C[M,40] = A[M,128] @ W[128,40] (W smem-resident, thread per row)
// ---------------------------------------------------------------------------
__global__ __launch_bounds__(128)
void gemm_n40(const float* __restrict__ A, const float* __restrict__ W,
              float* __restrict__ C, int M) {
    __shared__ float Ws[128][40];
    int tid = threadIdx.x;
    for (int i = tid; i < 128 * 40 / 4; i += 128)
        ((float4*)Ws)[i] = ((const float4*)W)[i];
    __syncthreads();
    int row = blockIdx.x * 128 + tid;
    if (row >= M) return;
    const float4* a4 = (const float4*)(A + (size_t)row * 128);
    float acc[40] = {};
    for (int kq = 0; kq < 32; kq++) {
        float4 a = a4[kq];
        float av[4] = {a.x, a.y, a.z, a.w};
#pragma unroll
        for (int j = 0; j < 4; j++) {
            const float4* wr = (const float4*)(&Ws[kq * 4 + j][0]);
            float aj = av[j];
#pragma unroll
            for (int c4 = 0; c4 < 10; c4++) {
                float4 w = wr[c4];
                acc[c4 * 4 + 0] += aj * w.x;
                acc[c4 * 4 + 1] += aj * w.y;
                acc[c4 * 4 + 2] += aj * w.z;
                acc[c4 * 4 + 3] += aj * w.w;
            }
        }
    }
    float* cp = C + (size_t)row * 40;
#pragma unroll
    for (int c4 = 0; c4 < 10; c4++)
        *(float4*)(cp + c4 * 4) =
            make_float4(acc[c4 * 4], acc[c4 * 4 + 1], acc[c4 * 4 + 2], acc[c4 * 4 + 3]);
}

// ---------------------------------------------------------------------------
// Elementwise kernels
// ---------------------------------------------------------------------------
__global__ void add_emb_k(const float* __restrict__ X, const float* __restrict__ emb,
                          const int* __restrict__ nw, float* __restrict__ H0, int M) {
    int i = blockIdx.x * blockDim.x + threadIdx.x;
    if (i >= M * 32) return;
    int r = i >> 5, c4 = i & 31;
    float4 x = ((const float4*)X)[i];
    float4 e = ((const float4*)(emb + (size_t)nw[r] * NH))[c4];
    ((float4*)H0)[i] = make_float4(x.x + e.x, x.y + e.y, x.z + e.z, x.w + e.w);
}
// level-1 combine fused with level-2 pool: c1 = combine(...); p2[assign1[r]] += c1
__global__ void combine_pool_k(const float* __restrict__ H0, const float* __restrict__ MSG,
                               const float* __restrict__ pa, const float* __restrict__ pb,
                               float* __restrict__ OUT, const int* __restrict__ assign,
                               float* __restrict__ P, int M) {
    int i = blockIdx.x * blockDim.x + threadIdx.x;
    if (i >= M * 32) return;
    int r = i >> 5, c4 = i & 31;
    float a = *pa, b = *pb, inv = 1.f / (a + b);
    float4 h = ((const float4*)H0)[i];
    float4 m = ((const float4*)MSG)[i];
    float4 o = make_float4((a * h.x + b * m.x) * inv, (a * h.y + b * m.y) * inv,
                           (a * h.z + b * m.z) * inv, (a * h.w + b * m.w) * inv);
    ((float4*)OUT)[i] = o;
    red_add_v4(((float4*)(P + (size_t)assign[r] * NH)) + c4, o.x, o.y, o.z, o.w);
}
__global__ void combine_k(const float* __restrict__ H0, const float* __restrict__ MSG,
                          const float* __restrict__ pa, const float* __restrict__ pb,
                          float* __restrict__ OUT, int total4) {
    int i = blockIdx.x * blockDim.x + threadIdx.x;
    if (i >= total4) return;
    float a = *pa, b = *pb, inv = 1.f / (a + b);
    float4 h = ((const float4*)H0)[i];
    float4 m = ((const float4*)MSG)[i];
    ((float4*)OUT)[i] = make_float4((a * h.x + b * m.x) * inv, (a * h.y + b * m.y) * inv,
                                    (a * h.z + b * m.z) * inv, (a * h.w + b * m.w) * inv);
}
// crf[r] = c2[assign1[assign0[r]]] + c1[assign0[r]] + gcn[r]
__global__ void unpool2_k(const float* __restrict__ c2, const float* __restrict__ c1,
                          const float* __restrict__ gcn,
                          const int* __restrict__ assign0, const int* __restrict__ assign1,
                          float* __restrict__ crf) {
    int w = (blockIdx.x * blockDim.x + threadIdx.x) >> 5;
    int lane = threadIdx.x & 31;
    if (w >= N0) return;
    int a0 = assign0[w];
    int a1 = assign1[a0];
    float4 v2 = ((const float4*)(c2 + (size_t)a1 * NH))[lane];
    float4 v1 = ((const float4*)(c1 + (size_t)a0 * NH))[lane];
    float4 vg = ((const float4*)(gcn + (size_t)w * NH))[lane];
    ((float4*)(crf + (size_t)w * NH))[lane] =
        make_float4(v2.x + v1.x + vg.x, v2.y + v1.y + vg.y,
                    v2.z + v1.z + vg.z, v2.w + v1.w + vg.w);
}

// ---------------------------------------------------------------------------
// CRF edge kernels
// ---------------------------------------------------------------------------
__global__ void edge_logits_k(const int* __restrict__ dsts, const int* __restrict__ srcs,
                              const float* __restrict__ Q, const float* __restrict__ Km,
                              float* __restrict__ logit, unsigned* __restrict__ mx, int E) {
    int w = (blockIdx.x * blockDim.x + threadIdx.x) >> 5;
    int lane = threadIdx.x & 31;
    if (w >= E) return;
    int dst = dsts[w], src = srcs[w];
    float4 q = ((const float4*)(Q + (size_t)dst * NH))[lane];
    float4 k = ((const float4*)(Km + (size_t)src * NH))[lane];
    float acc = q.x * k.x + q.y * k.y + q.z * k.z + q.w * k.w;
#pragma unroll
    for (int o = 16; o; o >>= 1) acc += __shfl_xor_sync(0xFFFFFFFFu, acc, o);
    if (lane == 0) {
        float l = acc * 0.08838834764831845f;
        logit[w] = l;
        atomicMax(mx + dst, f2ord(l));
    }
}
__global__ void edge_expsum_k(const int* __restrict__ dsts, float* __restrict__ logit,
                              const unsigned* __restrict__ mx, float* __restrict__ z, int E) {
    int e = blockIdx.x * blockDim.x + threadIdx.x;
    if (e >= E) return;
    int dst = dsts[e];
    float m = ord2f(mx[dst]);
    float ex = __expf(logit[e] - m);
    logit[e] = ex;
    atomicAdd(z + dst, ex);
}
__global__ void edge_msg_k(const int* __restrict__ dsts, const int* __restrict__ srcs,
                           const float* __restrict__ ev, const float* __restrict__ z,
                           const float* __restrict__ H0, float* __restrict__ MSG, int E) {
    int w = (blockIdx.x * blockDim.x + threadIdx.x) >> 5;
    int lane = threadIdx.x & 31;
    if (w >= E) return;
    int dst = dsts[w], src = srcs[w];
    float c = ev[w] / (z[dst] + 1e-16f);
    float4 a = ((const float4*)(H0 + (size_t)src * NH))[lane];
    float4* yd = ((float4*)(MSG + (size_t)dst * NH)) + lane;
    red_add_v4(yd, a.x * c, a.y * c, a.z * c, a.w * c);
}

// ---------------------------------------------------------------------------
// Host launch
// ---------------------------------------------------------------------------
static inline int cdiv(long long a, long long b) { return (int)((a + b - 1) / b); }

extern "C" void kernel_launch(void* const* d_in, const int* in_sizes, int n_in,
                              void* d_out, int out_size) {
    const float* x       = (const float*)d_in[0];
    const int*   A0      = (const int*)d_in[1];
    const float* A0v     = (const float*)d_in[2];
    const int*   A1      = (const int*)d_in[3];
    const float* A1v     = (const float*)d_in[4];
    const int*   A2      = (const int*)d_in[5];
    const float* A2v     = (const float*)d_in[6];
    const int*   assign0 = (const int*)d_in[7];
    const int*   assign1 = (const int*)d_in[8];
    const int*   nwgt1   = (const int*)d_in[9];
    const int*   nwgt2   = (const int*)d_in[10];
    const float* gc1_W   = (const float*)d_in[11];
    const float* gc1_b   = (const float*)d_in[12];
    const float* gc2_W   = (const float*)d_in[13];
    const float* gc2_b   = (const float*)d_in[14];
    const float* c1Wq    = (const float*)d_in[15];
    const float* c1Wk    = (const float*)d_in[16];
    const float* c1emb   = (const float*)d_in[17];
    const float* c1a     = (const float*)d_in[18];
    const float* c1b     = (const float*)d_in[19];
    const float* c2Wq    = (const float*)d_in[20];
    const float* c2Wk    = (const float*)d_in[21];
    const float* c2emb   = (const float*)d_in[22];
    const float* c2a     = (const float*)d_in[23];
    const float* c2b     = (const float*)d_in[24];

    float* out = (float*)d_out;                       // [N0, NC]
    float* gcn = out + (size_t)N0 * NC;               // [N0, NH]
    float* crf = gcn + (size_t)N0 * NH;               // [N0, NH]

    void *p_xW, *p_p1, *p_q1, *p_k1, *p_h01, *p_msg1, *p_c1;
    void *p_p2, *p_q2, *p_k2, *p_h02, *p_msg2, *p_c2, *p_hW2;
    void *p_l1, *p_z1, *p_m1, *p_l2, *p_z2, *p_m2;
    void *p_cnt, *p_rp, *p_bs, *p_es, *p_ev;
    cudaGetSymbolAddress(&p_xW, g_xW);   cudaGetSymbolAddress(&p_p1, g_p1);
    cudaGetSymbolAddress(&p_q1, g_q1);   cudaGetSymbolAddress(&p_k1, g_k1);
    cudaGetSymbolAddress(&p_h01, g_h01); cudaGetSymbolAddress(&p_msg1, g_msg1);
    cudaGetSymbolAddress(&p_c1, g_c1);
    cudaGetSymbolAddress(&p_p2, g_p2);   cudaGetSymbolAddress(&p_q2, g_q2);
    cudaGetSymbolAddress(&p_k2, g_k2);   cudaGetSymbolAddress(&p_h02, g_h02);
    cudaGetSymbolAddress(&p_msg2, g_msg2); cudaGetSymbolAddress(&p_c2, g_c2);
    cudaGetSymbolAddress(&p_hW2, g_hW2);
    cudaGetSymbolAddress(&p_l1, g_logit1); cudaGetSymbolAddress(&p_z1, g_z1);
    cudaGetSymbolAddress(&p_m1, g_max1);
    cudaGetSymbolAddress(&p_l2, g_logit2); cudaGetSymbolAddress(&p_z2, g_z2);
    cudaGetSymbolAddress(&p_m2, g_max2);
    cudaGetSymbolAddress(&p_cnt, g_cnt); cudaGetSymbolAddress(&p_rp, g_rowptr);
    cudaGetSymbolAddress(&p_bs, g_bsum); cudaGetSymbolAddress(&p_es, g_esrc);
    cudaGetSymbolAddress(&p_ev, g_eval);

    float* xW  = (float*)p_xW;  float* p1 = (float*)p_p1;  float* q1 = (float*)p_q1;
    float* k1  = (float*)p_k1;  float* h01 = (float*)p_h01; float* msg1 = (float*)p_msg1;
    float* c1  = (float*)p_c1;
    float* p2  = (float*)p_p2;  float* q2 = (float*)p_q2;  float* k2 = (float*)p_k2;
    float* h02 = (float*)p_h02; float* msg2 = (float*)p_msg2; float* c2 = (float*)p_c2;
    float* hW2 = (float*)p_hW2;
    float* l1 = (float*)p_l1; float* z1 = (float*)p_z1; unsigned* m1 = (unsigned*)p_m1;
    float* l2 = (float*)p_l2; float* z2 = (float*)p_z2; unsigned* m2 = (unsigned*)p_m2;
    int* cnt = (int*)p_cnt; int* rowptr = (int*)p_rp; int* bsum = (int*)p_bs;
    int* esrc = (int*)p_es; float* eval = (float*)p_ev;

    const int TB = 256;
    const int NBLK = cdiv(N0, 1024);   // 98 scan blocks

    // ---- Build dst-CSR of A0 (overlaps with gemm work conceptually; serial stream) ----
    cudaMemsetAsync(cnt, 0, N0 * 4);
    hist_k<<<cdiv(E0, TB), TB>>>(A0, cnt, E0);
    scan1_k<<<NBLK, 256>>>(cnt, rowptr, bsum, N0);
    scan2_k<<<1, 32>>>(bsum, NBLK);
    scan3_k<<<cdiv(N0, TB), TB>>>(rowptr, bsum, N0);
    cudaMemsetAsync(cnt, 0, N0 * 4);
    scatter_edges_k<<<cdiv(E0, TB), TB>>>(A0, A0 + E0, A0v, rowptr, cnt, esrc, eval, E0);

    // ---- GCN layer 1 GEMM: xW = x @ W1 ----
    {
        dim3 g(1, cdiv(N0, BM));
        gemm_nk128<<<g, 256>>>(x, gc1_W, gc1_W, xW, xW, N0);
    }

    // ---- Fused: gcn = relu(A0 @ xW + b1); p1[assign0] += gcn ----
    cudaMemsetAsync(p1, 0, (size_t)N1 * NH * 4);
    spmm_csr128_fused<<<cdiv((long long)N0 * 32, TB), TB>>>(rowptr, esrc, eval, xW,
                                                            gc1_b, gcn, assign0, p1);

    // ---- level 1 CRF ----
    {
        dim3 g(2, cdiv(N1, BM));
        gemm_nk128<<<g, 256>>>(p1, c1Wq, c1Wk, q1, k1, N1);
    }
    add_emb_k<<<cdiv((long long)N1 * 32, TB), TB>>>(p1, c1emb, nwgt1, h01, N1);
    cudaMemsetAsync(m1, 0, N1 * 4);
    cudaMemsetAsync(z1, 0, N1 * 4);
    cudaMemsetAsync(msg1, 0, (size_t)N1 * NH * 4);
    edge_logits_k<<<cdiv((long long)E1 * 32, TB), TB>>>(A1, A1 + E1, q1, k1, l1, m1, E1);
    edge_expsum_k<<<cdiv(E1, TB), TB>>>(A1, l1, m1, z1, E1);
    edge_msg_k<<<cdiv((long long)E1 * 32, TB), TB>>>(A1, A1 + E1, l1, z1, h01, msg1, E1);
    // combine (level1) fused with pool into p2
    cudaMemsetAsync(p2, 0, (size_t)N2 * NH * 4);
    combine_pool_k<<<cdiv((long long)N1 * 32, TB), TB>>>(h01, msg1, c1a, c1b, c1,
                                                         assign1, p2, N1);

    // ---- level 2 CRF ----
    {
        dim3 g(2, cdiv(N2, BM));
        gemm_nk128<<<g, 256>>>(p2, c2Wq, c2Wk, q2, k2, N2);
    }
    add_emb_k<<<cdiv((long long)N2 * 32, TB), TB>>>(p2, c2emb, nwgt2, h02, N2);
    cudaMemsetAsync(m2, 0, N2 * 4);
    cudaMemsetAsync(z2, 0, N2 * 4);
    cudaMemsetAsync(msg2, 0, (size_t)N2 * NH * 4);
    edge_logits_k<<<cdiv((long long)E2 * 32, TB), TB>>>(A2, A2 + E2, q2, k2, l2, m2, E2);
    edge_expsum_k<<<cdiv(E2, TB), TB>>>(A2, l2, m2, z2, E2);
    edge_msg_k<<<cdiv((long long)E2 * 32, TB), TB>>>(A2, A2 + E2, l2, z2, h02, msg2, E2);
    combine_k<<<cdiv((long long)N2 * NH / 4, TB), TB>>>(h02, msg2, c2a, c2b, c2, N2 * NH / 4);

    // ---- fused unpool with skips ----
    unpool2_k<<<cdiv((long long)N0 * 32, TB), TB>>>(c2, c1, gcn, assign0, assign1, crf);

    // ---- GCN layer 2: out = A0 @ (crf @ W2) + b2 ----
    gemm_n40<<<cdiv(N0, 128), 128>>>(crf, gc2_W, hW2, N0);
    spmm_csr40<<<cdiv((long long)N0 * 32, TB), TB>>>(rowptr, esrc, eval, hW2, gc2_b, out);
}

// round 8
// speedup vs baseline: 1.2781x; 1.2781x over previous
#include <cuda_runtime.h>
#include <cuda_bf16.h>
#include <cstdio>

// Problem constants
#define N0 100000
#define N1 25000
#define N2 6250
#define E0 1600000
#define E1 400000
#define E2 100000
#define NF 128
#define NH 128
#define NC 40

// ---------------------------------------------------------------------------
// Scratch (device globals — no allocation allowed)
// ---------------------------------------------------------------------------
__device__ __align__(16) float g_xW[(size_t)N0 * NH];
__device__ __align__(16) float g_p1[(size_t)N1 * NH];
__device__ __align__(16) float g_q1[(size_t)N1 * NH];
__device__ __align__(16) float g_k1[(size_t)N1 * NH];
__device__ __align__(16) float g_h01[(size_t)N1 * NH];
__device__ __align__(16) float g_msg1[(size_t)N1 * NH];
__device__ __align__(16) float g_c1[(size_t)N1 * NH];
__device__ __align__(16) float g_p2[(size_t)N2 * NH];
__device__ __align__(16) float g_q2[(size_t)N2 * NH];
__device__ __align__(16) float g_k2[(size_t)N2 * NH];
__device__ __align__(16) float g_h02[(size_t)N2 * NH];
__device__ __align__(16) float g_msg2[(size_t)N2 * NH];
__device__ __align__(16) float g_c2[(size_t)N2 * NH];
__device__ __align__(16) float g_hW2[(size_t)N0 * NC];
__device__ float g_logit1[E1];
__device__ float g_z1[N1];
__device__ unsigned g_max1[N1];
__device__ float g_logit2[E2];
__device__ float g_z2[N2];
__device__ unsigned g_max2[N2];
// CSR scratch for A0 (dst-sorted)
__device__ int   g_cnt[N0];
__device__ int   g_rowptr[N0 + 1];
__device__ int   g_bsum[128];
__device__ int   g_esrc[E0];
__device__ float g_eval[E0];

// ---------------------------------------------------------------------------
// Helpers
// ---------------------------------------------------------------------------
__device__ __forceinline__ unsigned f2ord(float f) {
    unsigned u = __float_as_uint(f);
    return (u & 0x80000000u) ? ~u : (u | 0x80000000u);
}
__device__ __forceinline__ float ord2f(unsigned u) {
    return __uint_as_float((u & 0x80000000u) ? (u & 0x7FFFFFFFu) : ~u);
}
__device__ __forceinline__ void red_add_v4(float4* addr, float a, float b, float c, float d) {
    asm volatile("red.global.add.v4.f32 [%0], {%1, %2, %3, %4};"
                 :: "l"(addr), "f"(a), "f"(b), "f"(c), "f"(d) : "memory");
}

// ---------------------------------------------------------------------------
// CSR build kernels
// ---------------------------------------------------------------------------
__global__ void hist_k(const int* __restrict__ dsts, int* __restrict__ cnt, int E) {
    int e = blockIdx.x * blockDim.x + threadIdx.x;
    if (e < E) atomicAdd(cnt + dsts[e], 1);
}
__global__ void scan1_k(const int* __restrict__ cnt, int* __restrict__ rowptr,
                        int* __restrict__ bsum, int n) {
    __shared__ int s[256];
    int t = threadIdx.x;
    int base = blockIdx.x * 1024 + t * 4;
    int v0 = (base + 0 < n) ? cnt[base + 0] : 0;
    int v1 = (base + 1 < n) ? cnt[base + 1] : 0;
    int v2 = (base + 2 < n) ? cnt[base + 2] : 0;
    int v3 = (base + 3 < n) ? cnt[base + 3] : 0;
    int x0 = v0, x1 = x0 + v1, x2 = x1 + v2, x3 = x2 + v3;
    s[t] = x3;
    __syncthreads();
    for (int off = 1; off < 256; off <<= 1) {
        int val = 0;
        if (t >= off) val = s[t - off];
        __syncthreads();
        if (t >= off) s[t] += val;
        __syncthreads();
    }
    int prev = (t > 0) ? s[t - 1] : 0;
    if (base + 0 < n) rowptr[base + 1] = prev + x0;
    if (base + 1 < n) rowptr[base + 2] = prev + x1;
    if (base + 2 < n) rowptr[base + 3] = prev + x2;
    if (base + 3 < n) rowptr[base + 4] = prev + x3;
    if (t == 255) bsum[blockIdx.x] = s[255];
}
// Parallel exclusive scan of up to 128 block sums (one block).
__global__ void scan2_k(int* __restrict__ bsum, int nb) {
    __shared__ int s[128];
    int t = threadIdx.x;
    int v = (t < nb) ? bsum[t] : 0;
    s[t] = v;
    __syncthreads();
    for (int off = 1; off < 128; off <<= 1) {
        int val = 0;
        if (t >= off) val = s[t - off];
        __syncthreads();
        if (t >= off) s[t] += val;
        __syncthreads();
    }
    if (t < nb) bsum[t] = s[t] - v;   // exclusive
}
__global__ void scan3_k(int* __restrict__ rowptr, const int* __restrict__ bsum, int n) {
    int i = blockIdx.x * blockDim.x + threadIdx.x;
    if (i == 0) rowptr[0] = 0;
    if (i < n) rowptr[i + 1] += bsum[i >> 10];
}
__global__ void scatter_edges_k(const int* __restrict__ dsts, const int* __restrict__ srcs,
                                const float* __restrict__ val, const int* __restrict__ rowptr,
                                int* __restrict__ cur, int* __restrict__ esrc,
                                float* __restrict__ eval, int E) {
    int e = blockIdx.x * blockDim.x + threadIdx.x;
    if (e >= E) return;
    int d = dsts[e];
    int pos = rowptr[d] + atomicAdd(cur + d, 1);
    esrc[pos] = srcs[e];
    eval[pos] = val[e];
}

// ---------------------------------------------------------------------------
// CSR SpMM (128 feats) fused, MLP-8 batched gathers:
// gcn = relu(A0 @ X + b); p1[assign0] += gcn
// ---------------------------------------------------------------------------
__global__ __launch_bounds__(256)
void spmm_csr128_fused(const int* __restrict__ rowptr, const int* __restrict__ esrc,
                       const float* __restrict__ eval, const float* __restrict__ X,
                       const float* __restrict__ bias, float* __restrict__ gcn,
                       const int* __restrict__ assign0, float* __restrict__ p1) {
    int w = (blockIdx.x * blockDim.x + threadIdx.x) >> 5;
    int lane = threadIdx.x & 31;
    if (w >= N0) return;
    int s = rowptr[w], e = rowptr[w + 1];
    float4 acc = ((const float4*)bias)[lane];
    const float4* X4 = (const float4*)X;

    for (int i = s; i < e; i += 8) {
        int nb = e - i; if (nb > 8) nb = 8;
        int   src_l = (lane < nb) ? esrc[i + lane] : 0;
        float val_l = (lane < nb) ? eval[i + lane] : 0.f;
        float4 a[8];
#pragma unroll
        for (int j = 0; j < 8; j++) {
            int s0 = __shfl_sync(0xFFFFFFFFu, src_l, j);
            if (j < nb) a[j] = X4[(size_t)s0 * 32 + lane];
        }
#pragma unroll
        for (int j = 0; j < 8; j++) {
            float v0 = __shfl_sync(0xFFFFFFFFu, val_l, j);
            if (j < nb) {
                acc.x += v0 * a[j].x; acc.y += v0 * a[j].y;
                acc.z += v0 * a[j].z; acc.w += v0 * a[j].w;
            }
        }
    }
    acc.x = fmaxf(acc.x, 0.f); acc.y = fmaxf(acc.y, 0.f);
    acc.z = fmaxf(acc.z, 0.f); acc.w = fmaxf(acc.w, 0.f);
    ((float4*)(gcn + (size_t)w * NH))[lane] = acc;
    int d = assign0[w];
    red_add_v4(((float4*)(p1 + (size_t)d * NH)) + lane, acc.x, acc.y, acc.z, acc.w);
}

// ---------------------------------------------------------------------------
// CSR SpMM (40 feats), MLP-8 batched: out = A0 @ X + b2.  Lanes 0..9 active
// for gathers/accumulation; all 32 lanes cooperate in (src,val) staging.
// ---------------------------------------------------------------------------
__global__ __launch_bounds__(256)
void spmm_csr40(const int* __restrict__ rowptr, const int* __restrict__ esrc,
                const float* __restrict__ eval, const float* __restrict__ X,
                const float* __restrict__ bias, float* __restrict__ out) {
    int w = (blockIdx.x * blockDim.x + threadIdx.x) >> 5;
    int lane = threadIdx.x & 31;
    if (w >= N0) return;
    int s = rowptr[w], e = rowptr[w + 1];
    bool act = lane < 10;
    float4 acc = act ? ((const float4*)bias)[lane] : make_float4(0, 0, 0, 0);
    const float4* X4 = (const float4*)X;

    for (int i = s; i < e; i += 8) {
        int nb = e - i; if (nb > 8) nb = 8;
        int   src_l = (lane < nb) ? esrc[i + lane] : 0;
        float val_l = (lane < nb) ? eval[i + lane] : 0.f;
        float4 a[8];
#pragma unroll
        for (int j = 0; j < 8; j++) {
            int s0 = __shfl_sync(0xFFFFFFFFu, src_l, j);
            if (j < nb && act) a[j] = X4[(size_t)s0 * 10 + lane];
        }
#pragma unroll
        for (int j = 0; j < 8; j++) {
            float v0 = __shfl_sync(0xFFFFFFFFu, val_l, j);
            if (j < nb && act) {
                acc.x += v0 * a[j].x; acc.y += v0 * a[j].y;
                acc.z += v0 * a[j].z; acc.w += v0 * a[j].w;
            }
        }
    }
    if (act) ((float4*)(out + (size_t)w * NC))[lane] = acc;
}

// ---------------------------------------------------------------------------
// SGEMM specialized for N = K = 128 (dual-output launch)
// ---------------------------------------------------------------------------
#define BM 128
#define BN 128
#define BKK 16
__global__ __launch_bounds__(256, 2)
void gemm_nk128(const float* __restrict__ A,
                const float* __restrict__ Ba, const float* __restrict__ Bb,
                float* __restrict__ Ca, float* __restrict__ Cb, int M) {
    __shared__ float As[BKK][BM + 4];
    __shared__ float Bs[BKK][BN];
    const float* __restrict__ B = (blockIdx.x == 0) ? Ba : Bb;
    float* __restrict__ C = (blockIdx.x == 0) ? Ca : Cb;

    int tid = threadIdx.x;
    int row0 = blockIdx.y * BM;
    int trow = tid >> 4;
    int tcol = tid & 15;

    float acc[8][8] = {};
    float a_reg[8], b_reg[8];

    for (int k0 = 0; k0 < 128; k0 += BKK) {
#pragma unroll
        for (int i = 0; i < 2; i++) {
            int idx = tid + i * 256;
            int r = idx >> 2;
            int kq = idx & 3;
            float4 v = make_float4(0.f, 0.f, 0.f, 0.f);
            int gr = row0 + r;
            if (gr < M)
                v = *(const float4*)(A + (size_t)gr * 128 + k0 + kq * 4);
            As[kq * 4 + 0][r] = v.x;
            As[kq * 4 + 1][r] = v.y;
            As[kq * 4 + 2][r] = v.z;
            As[kq * 4 + 3][r] = v.w;
        }
#pragma unroll
        for (int i = 0; i < 2; i++) {
            int idx = tid + i * 256;
            int r = idx >> 5;
            int c4 = idx & 31;
            float4 v = *(const float4*)(B + (size_t)(k0 + r) * 128 + c4 * 4);
            *(float4*)(&Bs[r][c4 * 4]) = v;
        }
        __syncthreads();
#pragma unroll
        for (int kk = 0; kk < BKK; kk++) {
            *(float4*)(a_reg)     = *(const float4*)(&As[kk][trow * 8]);
            *(float4*)(a_reg + 4) = *(const float4*)(&As[kk][trow * 8 + 4]);
            *(float4*)(b_reg)     = *(const float4*)(&Bs[kk][tcol * 8]);
            *(float4*)(b_reg + 4) = *(const float4*)(&Bs[kk][tcol * 8 + 4]);
#pragma unroll
            for (int i = 0; i < 8; i++)
#pragma unroll
                for (int j = 0; j < 8; j++)
                    acc[i][j] += a_reg[i] * b_reg[j];
        }
        __syncthreads();
    }
#pragma unroll
    for (int i = 0; i < 8; i++) {
        int gr = row0 + trow * 8 + i;
        if (gr >= M) continue;
        float* cp = C + (size_t)gr * 128 + tcol * 8;
        *(float4*)(cp)     = make_float4(acc[i][0], acc[i][1], acc[i][2], acc[i][3]);
        *(float4*)(cp + 4) = make_float4(acc[i][4], acc[i][5], acc[i][6], acc[i][7]);
    }
}

// ---------------------------------------------------------------------------
// GEMM for C[M,40] = A[M,128] @ W[128,40]
// ---------------------------------------------------------------------------
__global__ __launch_bounds__(128)
void gemm_n40(const float* __restrict__ A, const float* __restrict__ W,
              float* __restrict__ C, int M) {
    __shared__ float Ws[128][40];
    int tid = threadIdx.x;
    for (int i = tid; i < 128 * 40 / 4; i += 128)
        ((float4*)Ws)[i] = ((const float4*)W)[i];
    __syncthreads();
    int row = blockIdx.x * 128 + tid;
    if (row >= M) return;
    const float4* a4 = (const float4*)(A + (size_t)row * 128);
    float acc[40] = {};
    for (int kq = 0; kq < 32; kq++) {
        float4 a = a4[kq];
        float av[4] = {a.x, a.y, a.z, a.w};
#pragma unroll
        for (int j = 0; j < 4; j++) {
            const float4* wr = (const float4*)(&Ws[kq * 4 + j][0]);
            float aj = av[j];
#pragma unroll
            for (int c4 = 0; c4 < 10; c4++) {
                float4 w = wr[c4];
                acc[c4 * 4 + 0] += aj * w.x;
                acc[c4 * 4 + 1] += aj * w.y;
                acc[c4 * 4 + 2] += aj * w.z;
                acc[c4 * 4 + 3] += aj * w.w;
            }
        }
    }
    float* cp = C + (size_t)row * 40;
#pragma unroll
    for (int c4 = 0; c4 < 10; c4++)
        *(float4*)(cp + c4 * 4) =
            make_float4(acc[c4 * 4], acc[c4 * 4 + 1], acc[c4 * 4 + 2], acc[c4 * 4 + 3]);
}

// ---------------------------------------------------------------------------
// Elementwise kernels
// ---------------------------------------------------------------------------
__global__ void add_emb_k(const float* __restrict__ X, const float* __restrict__ emb,
                          const int* __restrict__ nw, float* __restrict__ H0, int M) {
    int i = blockIdx.x * blockDim.x + threadIdx.x;
    if (i >= M * 32) return;
    int r = i >> 5, c4 = i & 31;
    float4 x = ((const float4*)X)[i];
    float4 e = ((const float4*)(emb + (size_t)nw[r] * NH))[c4];
    ((float4*)H0)[i] = make_float4(x.x + e.x, x.y + e.y, x.z + e.z, x.w + e.w);
}
__global__ void combine_pool_k(const float* __restrict__ H0, const float* __restrict__ MSG,
                               const float* __restrict__ pa, const float* __restrict__ pb,
                               float* __restrict__ OUT, const int* __restrict__ assign,
                               float* __restrict__ P, int M) {
    int i = blockIdx.x * blockDim.x + threadIdx.x;
    if (i >= M * 32) return;
    int r = i >> 5, c4 = i & 31;
    float a = *pa, b = *pb, inv = 1.f / (a + b);
    float4 h = ((const float4*)H0)[i];
    float4 m = ((const float4*)MSG)[i];
    float4 o = make_float4((a * h.x + b * m.x) * inv, (a * h.y + b * m.y) * inv,
                           (a * h.z + b * m.z) * inv, (a * h.w + b * m.w) * inv);
    ((float4*)OUT)[i] = o;
    red_add_v4(((float4*)(P + (size_t)assign[r] * NH)) + c4, o.x, o.y, o.z, o.w);
}
__global__ void combine_k(const float* __restrict__ H0, const float* __restrict__ MSG,
                          const float* __restrict__ pa, const float* __restrict__ pb,
                          float* __restrict__ OUT, int total4) {
    int i = blockIdx.x * blockDim.x + threadIdx.x;
    if (i >= total4) return;
    float a = *pa, b = *pb, inv = 1.f / (a + b);
    float4 h = ((const float4*)H0)[i];
    float4 m = ((const float4*)MSG)[i];
    ((float4*)OUT)[i] = make_float4((a * h.x + b * m.x) * inv, (a * h.y + b * m.y) * inv,
                                    (a * h.z + b * m.z) * inv, (a * h.w + b * m.w) * inv);
}
__global__ void unpool2_k(const float* __restrict__ c2, const float* __restrict__ c1,
                          const float* __restrict__ gcn,
                          const int* __restrict__ assign0, const int* __restrict__ assign1,
                          float* __restrict__ crf) {
    int w = (blockIdx.x * blockDim.x + threadIdx.x) >> 5;
    int lane = threadIdx.x & 31;
    if (w >= N0) return;
    int a0 = assign0[w];
    int a1 = assign1[a0];
    float4 v2 = ((const float4*)(c2 + (size_t)a1 * NH))[lane];
    float4 v1 = ((const float4*)(c1 + (size_t)a0 * NH))[lane];
    float4 vg = ((const float4*)(gcn + (size_t)w * NH))[lane];
    ((float4*)(crf + (size_t)w * NH))[lane] =
        make_float4(v2.x + v1.x + vg.x, v2.y + v1.y + vg.y,
                    v2.z + v1.z + vg.z, v2.w + v1.w + vg.w);
}

// ---------------------------------------------------------------------------
// CRF edge kernels
// ---------------------------------------------------------------------------
__global__ void edge_logits_k(const int* __restrict__ dsts, const int* __restrict__ srcs,
                              const float* __restrict__ Q, const float* __restrict__ Km,
                              float* __restrict__ logit, unsigned* __restrict__ mx, int E) {
    int w = (blockIdx.x * blockDim.x + threadIdx.x) >> 5;
    int lane = threadIdx.x & 31;
    if (w >= E) return;
    int dst = dsts[w], src = srcs[w];
    float4 q = ((const float4*)(Q + (size_t)dst * NH))[lane];
    float4 k = ((const float4*)(Km + (size_t)src * NH))[lane];
    float acc = q.x * k.x + q.y * k.y + q.z * k.z + q.w * k.w;
#pragma unroll
    for (int o = 16; o; o >>= 1) acc += __shfl_xor_sync(0xFFFFFFFFu, acc, o);
    if (lane == 0) {
        float l = acc * 0.08838834764831845f;
        logit[w] = l;
        atomicMax(mx + dst, f2ord(l));
    }
}
__global__ void edge_expsum_k(const int* __restrict__ dsts, float* __restrict__ logit,
                              const unsigned* __restrict__ mx, float* __restrict__ z, int E) {
    int e = blockIdx.x * blockDim.x + threadIdx.x;
    if (e >= E) return;
    int dst = dsts[e];
    float m = ord2f(mx[dst]);
    float ex = __expf(logit[e] - m);
    logit[e] = ex;
    atomicAdd(z + dst, ex);
}
__global__ void edge_msg_k(const int* __restrict__ dsts, const int* __restrict__ srcs,
                           const float* __restrict__ ev, const float* __restrict__ z,
                           const float* __restrict__ H0, float* __restrict__ MSG, int E) {
    int w = (blockIdx.x * blockDim.x + threadIdx.x) >> 5;
    int lane = threadIdx.x & 31;
    if (w >= E) return;
    int dst = dsts[w], src = srcs[w];
    float c = ev[w] / (z[dst] + 1e-16f);
    float4 a = ((const float4*)(H0 + (size_t)src * NH))[lane];
    float4* yd = ((float4*)(MSG + (size_t)dst * NH)) + lane;
    red_add_v4(yd, a.x * c, a.y * c, a.z * c, a.w * c);
}

// ---------------------------------------------------------------------------
// Host launch
// ---------------------------------------------------------------------------
static inline int cdiv(long long a, long long b) { return (int)((a + b - 1) / b); }

extern "C" void kernel_launch(void* const* d_in, const int* in_sizes, int n_in,
                              void* d_out, int out_size) {
    const float* x       = (const float*)d_in[0];
    const int*   A0      = (const int*)d_in[1];
    const float* A0v     = (const float*)d_in[2];
    const int*   A1      = (const int*)d_in[3];
    const float* A1v     = (const float*)d_in[4];
    const int*   A2      = (const int*)d_in[5];
    const float* A2v     = (const float*)d_in[6];
    const int*   assign0 = (const int*)d_in[7];
    const int*   assign1 = (const int*)d_in[8];
    const int*   nwgt1   = (const int*)d_in[9];
    const int*   nwgt2   = (const int*)d_in[10];
    const float* gc1_W   = (const float*)d_in[11];
    const float* gc1_b   = (const float*)d_in[12];
    const float* gc2_W   = (const float*)d_in[13];
    const float* gc2_b   = (const float*)d_in[14];
    const float* c1Wq    = (const float*)d_in[15];
    const float* c1Wk    = (const float*)d_in[16];
    const float* c1emb   = (const float*)d_in[17];
    const float* c1a     = (const float*)d_in[18];
    const float* c1b     = (const float*)d_in[19];
    const float* c2Wq    = (const float*)d_in[20];
    const float* c2Wk    = (const float*)d_in[21];
    const float* c2emb   = (const float*)d_in[22];
    const float* c2a     = (const float*)d_in[23];
    const float* c2b     = (const float*)d_in[24];

    float* out = (float*)d_out;                       // [N0, NC]
    float* gcn = out + (size_t)N0 * NC;               // [N0, NH]
    float* crf = gcn + (size_t)N0 * NH;               // [N0, NH]

    void *p_xW, *p_p1, *p_q1, *p_k1, *p_h01, *p_msg1, *p_c1;
    void *p_p2, *p_q2, *p_k2, *p_h02, *p_msg2, *p_c2, *p_hW2;
    void *p_l1, *p_z1, *p_m1, *p_l2, *p_z2, *p_m2;
    void *p_cnt, *p_rp, *p_bs, *p_es, *p_ev;
    cudaGetSymbolAddress(&p_xW, g_xW);   cudaGetSymbolAddress(&p_p1, g_p1);
    cudaGetSymbolAddress(&p_q1, g_q1);   cudaGetSymbolAddress(&p_k1, g_k1);
    cudaGetSymbolAddress(&p_h01, g_h01); cudaGetSymbolAddress(&p_msg1, g_msg1);
    cudaGetSymbolAddress(&p_c1, g_c1);
    cudaGetSymbolAddress(&p_p2, g_p2);   cudaGetSymbolAddress(&p_q2, g_q2);
    cudaGetSymbolAddress(&p_k2, g_k2);   cudaGetSymbolAddress(&p_h02, g_h02);
    cudaGetSymbolAddress(&p_msg2, g_msg2); cudaGetSymbolAddress(&p_c2, g_c2);
    cudaGetSymbolAddress(&p_hW2, g_hW2);
    cudaGetSymbolAddress(&p_l1, g_logit1); cudaGetSymbolAddress(&p_z1, g_z1);
    cudaGetSymbolAddress(&p_m1, g_max1);
    cudaGetSymbolAddress(&p_l2, g_logit2); cudaGetSymbolAddress(&p_z2, g_z2);
    cudaGetSymbolAddress(&p_m2, g_max2);
    cudaGetSymbolAddress(&p_cnt, g_cnt); cudaGetSymbolAddress(&p_rp, g_rowptr);
    cudaGetSymbolAddress(&p_bs, g_bsum); cudaGetSymbolAddress(&p_es, g_esrc);
    cudaGetSymbolAddress(&p_ev, g_eval);

    float* xW  = (float*)p_xW;  float* p1 = (float*)p_p1;  float* q1 = (float*)p_q1;
    float* k1  = (float*)p_k1;  float* h01 = (float*)p_h01; float* msg1 = (float*)p_msg1;
    float* c1  = (float*)p_c1;
    float* p2  = (float*)p_p2;  float* q2 = (float*)p_q2;  float* k2 = (float*)p_k2;
    float* h02 = (float*)p_h02; float* msg2 = (float*)p_msg2; float* c2 = (float*)p_c2;
    float* hW2 = (float*)p_hW2;
    float* l1 = (float*)p_l1; float* z1 = (float*)p_z1; unsigned* m1 = (unsigned*)p_m1;
    float* l2 = (float*)p_l2; float* z2 = (float*)p_z2; unsigned* m2 = (unsigned*)p_m2;
    int* cnt = (int*)p_cnt; int* rowptr = (int*)p_rp; int* bsum = (int*)p_bs;
    int* esrc = (int*)p_es; float* eval = (float*)p_ev;

    const int TB = 256;
    const int NBLK = cdiv(N0, 1024);   // 98 scan blocks

    // ---- Build dst-CSR of A0 ----
    cudaMemsetAsync(cnt, 0, N0 * 4);
    hist_k<<<cdiv(E0, TB), TB>>>(A0, cnt, E0);
    scan1_k<<<NBLK, 256>>>(cnt, rowptr, bsum, N0);
    scan2_k<<<1, 128>>>(bsum, NBLK);
    scan3_k<<<cdiv(N0, TB), TB>>>(rowptr, bsum, N0);
    cudaMemsetAsync(cnt, 0, N0 * 4);
    scatter_edges_k<<<cdiv(E0, TB), TB>>>(A0, A0 + E0, A0v, rowptr, cnt, esrc, eval, E0);

    // ---- GCN layer 1 GEMM: xW = x @ W1 ----
    {
        dim3 g(1, cdiv(N0, BM));
        gemm_nk128<<<g, 256>>>(x, gc1_W, gc1_W, xW, xW, N0);
    }

    // ---- Fused: gcn = relu(A0 @ xW + b1); p1[assign0] += gcn ----
    cudaMemsetAsync(p1, 0, (size_t)N1 * NH * 4);
    spmm_csr128_fused<<<cdiv((long long)N0 * 32, TB), TB>>>(rowptr, esrc, eval, xW,
                                                            gc1_b, gcn, assign0, p1);

    // ---- level 1 CRF ----
    {
        dim3 g(2, cdiv(N1, BM));
        gemm_nk128<<<g, 256>>>(p1, c1Wq, c1Wk, q1, k1, N1);
    }
    add_emb_k<<<cdiv((long long)N1 * 32, TB), TB>>>(p1, c1emb, nwgt1, h01, N1);
    cudaMemsetAsync(m1, 0, N1 * 4);
    cudaMemsetAsync(z1, 0, N1 * 4);
    cudaMemsetAsync(msg1, 0, (size_t)N1 * NH * 4);
    edge_logits_k<<<cdiv((long long)E1 * 32, TB), TB>>>(A1, A1 + E1, q1, k1, l1, m1, E1);
    edge_expsum_k<<<cdiv(E1, TB), TB>>>(A1, l1, m1, z1, E1);
    edge_msg_k<<<cdiv((long long)E1 * 32, TB), TB>>>(A1, A1 + E1, l1, z1, h01, msg1, E1);
    cudaMemsetAsync(p2, 0, (size_t)N2 * NH * 4);
    combine_pool_k<<<cdiv((long long)N1 * 32, TB), TB>>>(h01, msg1, c1a, c1b, c1,
                                                         assign1, p2, N1);

    // ---- level 2 CRF ----
    {
        dim3 g(2, cdiv(N2, BM));
        gemm_nk128<<<g, 256>>>(p2, c2Wq, c2Wk, q2, k2, N2);
    }
    add_emb_k<<<cdiv((long long)N2 * 32, TB), TB>>>(p2, c2emb, nwgt2, h02, N2);
    cudaMemsetAsync(m2, 0, N2 * 4);
    cudaMemsetAsync(z2, 0, N2 * 4);
    cudaMemsetAsync(msg2, 0, (size_t)N2 * NH * 4);
    edge_logits_k<<<cdiv((long long)E2 * 32, TB), TB>>>(A2, A2 + E2, q2, k2, l2, m2, E2);
    edge_expsum_k<<<cdiv(E2, TB), TB>>>(A2, l2, m2, z2, E2);
    edge_msg_k<<<cdiv((long long)E2 * 32, TB), TB>>>(A2, A2 + E2, l2, z2, h02, msg2, E2);
    combine_k<<<cdiv((long long)N2 * NH / 4, TB), TB>>>(h02, msg2, c2a, c2b, c2, N2 * NH / 4);

    // ---- fused unpool with skips ----
    unpool2_k<<<cdiv((long long)N0 * 32, TB), TB>>>(c2, c1, gcn, assign0, assign1, crf);

    // ---- GCN layer 2: out = A0 @ (crf @ W2) + b2 ----
    gemm_n40<<<cdiv(N0, 128), 128>>>(crf, gc2_W, hW2, N0);
    spmm_csr40<<<cdiv((long long)N0 * 32, TB), TB>>>(rowptr, esrc, eval, hW2, gc2_b, out);
}

// round 9
// speedup vs baseline: 1.2905x; 1.0097x over previous
#include <cuda_runtime.h>
#include <cuda_bf16.h>
#include <cstdio>

// Problem constants
#define N0 100000
#define N1 25000
#define N2 6250
#define E0 1600000
#define E1 400000
#define E2 100000
#define NF 128
#define NH 128
#define NC 40

// ---------------------------------------------------------------------------
// Scratch (device globals — no allocation allowed)
// ---------------------------------------------------------------------------
__device__ __align__(16) float g_xW[(size_t)N0 * NH];
__device__ __align__(16) float g_p1[(size_t)N1 * NH];
__device__ __align__(16) float g_q1[(size_t)N1 * NH];
__device__ __align__(16) float g_k1[(size_t)N1 * NH];
__device__ __align__(16) float g_h01[(size_t)N1 * NH];
__device__ __align__(16) float g_c1[(size_t)N1 * NH];
__device__ __align__(16) float g_p2[(size_t)N2 * NH];
__device__ __align__(16) float g_q2[(size_t)N2 * NH];
__device__ __align__(16) float g_k2[(size_t)N2 * NH];
__device__ __align__(16) float g_h02[(size_t)N2 * NH];
__device__ __align__(16) float g_c2[(size_t)N2 * NH];
__device__ __align__(16) float g_hW2[(size_t)N0 * NC];
// CSR scratch
__device__ int   g_cnt[N0];
__device__ int   g_bsum[128];
__device__ int   g_rowptr[N0 + 1];
__device__ int   g_esrc[E0];
__device__ float g_eval[E0];
__device__ int   g_rowptr1[N1 + 1];
__device__ int   g_ecol1[E1];
__device__ int   g_rowptr2[N2 + 1];
__device__ int   g_ecol2[E2];

// ---------------------------------------------------------------------------
// Helpers
// ---------------------------------------------------------------------------
__device__ __forceinline__ void red_add_v4(float4* addr, float a, float b, float c, float d) {
    asm volatile("red.global.add.v4.f32 [%0], {%1, %2, %3, %4};"
                 :: "l"(addr), "f"(a), "f"(b), "f"(c), "f"(d) : "memory");
}

// ---------------------------------------------------------------------------
// CSR build kernels
// ---------------------------------------------------------------------------
__global__ void hist_k(const int* __restrict__ dsts, int* __restrict__ cnt, int E) {
    int e = blockIdx.x * blockDim.x + threadIdx.x;
    if (e < E) atomicAdd(cnt + dsts[e], 1);
}
__global__ void scan1_k(const int* __restrict__ cnt, int* __restrict__ rowptr,
                        int* __restrict__ bsum, int n) {
    __shared__ int s[256];
    int t = threadIdx.x;
    int base = blockIdx.x * 1024 + t * 4;
    int v0 = (base + 0 < n) ? cnt[base + 0] : 0;
    int v1 = (base + 1 < n) ? cnt[base + 1] : 0;
    int v2 = (base + 2 < n) ? cnt[base + 2] : 0;
    int v3 = (base + 3 < n) ? cnt[base + 3] : 0;
    int x0 = v0, x1 = x0 + v1, x2 = x1 + v2, x3 = x2 + v3;
    s[t] = x3;
    __syncthreads();
    for (int off = 1; off < 256; off <<= 1) {
        int val = 0;
        if (t >= off) val = s[t - off];
        __syncthreads();
        if (t >= off) s[t] += val;
        __syncthreads();
    }
    int prev = (t > 0) ? s[t - 1] : 0;
    if (base + 0 < n) rowptr[base + 1] = prev + x0;
    if (base + 1 < n) rowptr[base + 2] = prev + x1;
    if (base + 2 < n) rowptr[base + 3] = prev + x2;
    if (base + 3 < n) rowptr[base + 4] = prev + x3;
    if (t == 255) bsum[blockIdx.x] = s[255];
}
__global__ void scan2_k(int* __restrict__ bsum, int nb) {
    __shared__ int s[128];
    int t = threadIdx.x;
    int v = (t < nb) ? bsum[t] : 0;
    s[t] = v;
    __syncthreads();
    for (int off = 1; off < 128; off <<= 1) {
        int val = 0;
        if (t >= off) val = s[t - off];
        __syncthreads();
        if (t >= off) s[t] += val;
        __syncthreads();
    }
    if (t < nb) bsum[t] = s[t] - v;   // exclusive
}
__global__ void scan3_k(int* __restrict__ rowptr, const int* __restrict__ bsum, int n) {
    int i = blockIdx.x * blockDim.x + threadIdx.x;
    if (i == 0) rowptr[0] = 0;
    if (i < n) rowptr[i + 1] += bsum[i >> 10];
}
__global__ void scatter_edges_k(const int* __restrict__ dsts, const int* __restrict__ srcs,
                                const float* __restrict__ val, const int* __restrict__ rowptr,
                                int* __restrict__ cur, int* __restrict__ esrc,
                                float* __restrict__ eval, int E) {
    int e = blockIdx.x * blockDim.x + threadIdx.x;
    if (e >= E) return;
    int d = dsts[e];
    int pos = rowptr[d] + atomicAdd(cur + d, 1);
    esrc[pos] = srcs[e];
    eval[pos] = val[e];
}
// CSR scatter, src only (edge values unused by CRF)
__global__ void scatter_src_k(const int* __restrict__ dsts, const int* __restrict__ srcs,
                              const int* __restrict__ rowptr, int* __restrict__ cur,
                              int* __restrict__ ecol, int E) {
    int e = blockIdx.x * blockDim.x + threadIdx.x;
    if (e >= E) return;
    int d = dsts[e];
    int pos = rowptr[d] + atomicAdd(cur + d, 1);
    ecol[pos] = srcs[e];
}

// ---------------------------------------------------------------------------
// CSR SpMM (128 feats) fused, MLP-8 batched gathers:
// gcn = relu(A0 @ X + b); p1[assign0] += gcn
// ---------------------------------------------------------------------------
__global__ __launch_bounds__(256)
void spmm_csr128_fused(const int* __restrict__ rowptr, const int* __restrict__ esrc,
                       const float* __restrict__ eval, const float* __restrict__ X,
                       const float* __restrict__ bias, float* __restrict__ gcn,
                       const int* __restrict__ assign0, float* __restrict__ p1) {
    int w = (blockIdx.x * blockDim.x + threadIdx.x) >> 5;
    int lane = threadIdx.x & 31;
    if (w >= N0) return;
    int s = rowptr[w], e = rowptr[w + 1];
    float4 acc = ((const float4*)bias)[lane];
    const float4* X4 = (const float4*)X;

    for (int i = s; i < e; i += 8) {
        int nb = e - i; if (nb > 8) nb = 8;
        int   src_l = (lane < nb) ? esrc[i + lane] : 0;
        float val_l = (lane < nb) ? eval[i + lane] : 0.f;
        float4 a[8];
#pragma unroll
        for (int j = 0; j < 8; j++) {
            int s0 = __shfl_sync(0xFFFFFFFFu, src_l, j);
            if (j < nb) a[j] = X4[(size_t)s0 * 32 + lane];
        }
#pragma unroll
        for (int j = 0; j < 8; j++) {
            float v0 = __shfl_sync(0xFFFFFFFFu, val_l, j);
            if (j < nb) {
                acc.x += v0 * a[j].x; acc.y += v0 * a[j].y;
                acc.z += v0 * a[j].z; acc.w += v0 * a[j].w;
            }
        }
    }
    acc.x = fmaxf(acc.x, 0.f); acc.y = fmaxf(acc.y, 0.f);
    acc.z = fmaxf(acc.z, 0.f); acc.w = fmaxf(acc.w, 0.f);
    ((float4*)(gcn + (size_t)w * NH))[lane] = acc;
    int d = assign0[w];
    red_add_v4(((float4*)(p1 + (size_t)d * NH)) + lane, acc.x, acc.y, acc.z, acc.w);
}

// ---------------------------------------------------------------------------
// CSR SpMM (40 feats), MLP-8 batched: out = A0 @ X + b2
// ---------------------------------------------------------------------------
__global__ __launch_bounds__(256)
void spmm_csr40(const int* __restrict__ rowptr, const int* __restrict__ esrc,
                const float* __restrict__ eval, const float* __restrict__ X,
                const float* __restrict__ bias, float* __restrict__ out) {
    int w = (blockIdx.x * blockDim.x + threadIdx.x) >> 5;
    int lane = threadIdx.x & 31;
    if (w >= N0) return;
    int s = rowptr[w], e = rowptr[w + 1];
    bool act = lane < 10;
    float4 acc = act ? ((const float4*)bias)[lane] : make_float4(0, 0, 0, 0);
    const float4* X4 = (const float4*)X;

    for (int i = s; i < e; i += 8) {
        int nb = e - i; if (nb > 8) nb = 8;
        int   src_l = (lane < nb) ? esrc[i + lane] : 0;
        float val_l = (lane < nb) ? eval[i + lane] : 0.f;
        float4 a[8];
#pragma unroll
        for (int j = 0; j < 8; j++) {
            int s0 = __shfl_sync(0xFFFFFFFFu, src_l, j);
            if (j < nb && act) a[j] = X4[(size_t)s0 * 10 + lane];
        }
#pragma unroll
        for (int j = 0; j < 8; j++) {
            float v0 = __shfl_sync(0xFFFFFFFFu, val_l, j);
            if (j < nb && act) {
                acc.x += v0 * a[j].x; acc.y += v0 * a[j].y;
                acc.z += v0 * a[j].z; acc.w += v0 * a[j].w;
            }
        }
    }
    if (act) ((float4*)(out + (size_t)w * NC))[lane] = acc;
}

// ---------------------------------------------------------------------------
// Fused CRF: one warp per dst row, online softmax over CSR edges.
// c[dst] = (a*h0[dst] + b*msg)/(a+b),  msg = softmax_row(q[dst]·k[src])·h0[src]
// If P != null, also P[assign[dst]] += c (next-level pool).
// ---------------------------------------------------------------------------
__global__ __launch_bounds__(256)
void crf_fused_k(const int* __restrict__ rowptr, const int* __restrict__ ecol,
                 const float* __restrict__ Q, const float* __restrict__ Km,
                 const float* __restrict__ H0,
                 const float* __restrict__ pa, const float* __restrict__ pb,
                 float* __restrict__ OUT, const int* __restrict__ assign,
                 float* __restrict__ P, int n) {
    int w = (blockIdx.x * blockDim.x + threadIdx.x) >> 5;
    int lane = threadIdx.x & 31;
    if (w >= n) return;
    int s = rowptr[w], e = rowptr[w + 1];
    const float4* K4 = (const float4*)Km;
    const float4* H4 = (const float4*)H0;

    float4 q4 = ((const float4*)(Q + (size_t)w * NH))[lane];

    float m = -3.4e38f, z = 0.f;
    float4 macc = make_float4(0.f, 0.f, 0.f, 0.f);

    for (int i = s; i < e; i += 8) {
        int nb = e - i; if (nb > 8) nb = 8;
        int src_l = (lane < nb) ? ecol[i + lane] : 0;
        float4 buf[8];
        // gather k[src] batch (MLP-8)
#pragma unroll
        for (int j = 0; j < 8; j++) {
            int s0 = __shfl_sync(0xFFFFFFFFu, src_l, j);
            if (j < nb) buf[j] = K4[(size_t)s0 * 32 + lane];
        }
        // warp-reduced dots -> logits (uniform across lanes)
        float lj[8];
#pragma unroll
        for (int j = 0; j < 8; j++) {
            if (j < nb) {
                float d = q4.x * buf[j].x + q4.y * buf[j].y +
                          q4.z * buf[j].z + q4.w * buf[j].w;
#pragma unroll
                for (int o = 16; o; o >>= 1) d += __shfl_xor_sync(0xFFFFFFFFu, d, o);
                lj[j] = d * 0.08838834764831845f;   // 1/sqrt(128)
            }
        }
        // online softmax rescale
        float bm = -3.4e38f;
#pragma unroll
        for (int j = 0; j < 8; j++) if (j < nb) bm = fmaxf(bm, lj[j]);
        float nm = fmaxf(m, bm);
        float sc = __expf(m - nm);
        z *= sc;
        macc.x *= sc; macc.y *= sc; macc.z *= sc; macc.w *= sc;
        m = nm;
        // gather h0[src] batch (reuse buf)
#pragma unroll
        for (int j = 0; j < 8; j++) {
            int s0 = __shfl_sync(0xFFFFFFFFu, src_l, j);
            if (j < nb) buf[j] = H4[(size_t)s0 * 32 + lane];
        }
#pragma unroll
        for (int j = 0; j < 8; j++) {
            if (j < nb) {
                float ej = __expf(lj[j] - m);
                z += ej;
                macc.x += ej * buf[j].x; macc.y += ej * buf[j].y;
                macc.z += ej * buf[j].z; macc.w += ej * buf[j].w;
            }
        }
    }
    float coef = 1.f / (z + 1e-16f);
    float a = *pa, b = *pb, inv = 1.f / (a + b);
    float4 h0d = H4[(size_t)w * 32 + lane];
    float4 c = make_float4((a * h0d.x + b * macc.x * coef) * inv,
                           (a * h0d.y + b * macc.y * coef) * inv,
                           (a * h0d.z + b * macc.z * coef) * inv,
                           (a * h0d.w + b * macc.w * coef) * inv);
    ((float4*)(OUT + (size_t)w * NH))[lane] = c;
    if (P) {
        int d = assign[w];
        red_add_v4(((float4*)(P + (size_t)d * NH)) + lane, c.x, c.y, c.z, c.w);
    }
}

// ---------------------------------------------------------------------------
// SGEMM specialized for N = K = 128 (dual-output launch)
// ---------------------------------------------------------------------------
#define BM 128
#define BN 128
#define BKK 16
__global__ __launch_bounds__(256, 2)
void gemm_nk128(const float* __restrict__ A,
                const float* __restrict__ Ba, const float* __restrict__ Bb,
                float* __restrict__ Ca, float* __restrict__ Cb, int M) {
    __shared__ float As[BKK][BM + 4];
    __shared__ float Bs[BKK][BN];
    const float* __restrict__ B = (blockIdx.x == 0) ? Ba : Bb;
    float* __restrict__ C = (blockIdx.x == 0) ? Ca : Cb;

    int tid = threadIdx.x;
    int row0 = blockIdx.y * BM;
    int trow = tid >> 4;
    int tcol = tid & 15;

    float acc[8][8] = {};
    float a_reg[8], b_reg[8];

    for (int k0 = 0; k0 < 128; k0 += BKK) {
#pragma unroll
        for (int i = 0; i < 2; i++) {
            int idx = tid + i * 256;
            int r = idx >> 2;
            int kq = idx & 3;
            float4 v = make_float4(0.f, 0.f, 0.f, 0.f);
            int gr = row0 + r;
            if (gr < M)
                v = *(const float4*)(A + (size_t)gr * 128 + k0 + kq * 4);
            As[kq * 4 + 0][r] = v.x;
            As[kq * 4 + 1][r] = v.y;
            As[kq * 4 + 2][r] = v.z;
            As[kq * 4 + 3][r] = v.w;
        }
#pragma unroll
        for (int i = 0; i < 2; i++) {
            int idx = tid + i * 256;
            int r = idx >> 5;
            int c4 = idx & 31;
            float4 v = *(const float4*)(B + (size_t)(k0 + r) * 128 + c4 * 4);
            *(float4*)(&Bs[r][c4 * 4]) = v;
        }
        __syncthreads();
#pragma unroll
        for (int kk = 0; kk < BKK; kk++) {
            *(float4*)(a_reg)     = *(const float4*)(&As[kk][trow * 8]);
            *(float4*)(a_reg + 4) = *(const float4*)(&As[kk][trow * 8 + 4]);
            *(float4*)(b_reg)     = *(const float4*)(&Bs[kk][tcol * 8]);
            *(float4*)(b_reg + 4) = *(const float4*)(&Bs[kk][tcol * 8 + 4]);
#pragma unroll
            for (int i = 0; i < 8; i++)
#pragma unroll
                for (int j = 0; j < 8; j++)
                    acc[i][j] += a_reg[i] * b_reg[j];
        }
        __syncthreads();
    }
#pragma unroll
    for (int i = 0; i < 8; i++) {
        int gr = row0 + trow * 8 + i;
        if (gr >= M) continue;
        float* cp = C + (size_t)gr * 128 + tcol * 8;
        *(float4*)(cp)     = make_float4(acc[i][0], acc[i][1], acc[i][2], acc[i][3]);
        *(float4*)(cp + 4) = make_float4(acc[i][4], acc[i][5], acc[i][6], acc[i][7]);
    }
}

// ---------------------------------------------------------------------------
// GEMM for C[M,40] = A[M,128] @ W[128,40]
// ---------------------------------------------------------------------------
__global__ __launch_bounds__(128)
void gemm_n40(const float* __restrict__ A, const float* __restrict__ W,
              float* __restrict__ C, int M) {
    __shared__ float Ws[128][40];
    int tid = threadIdx.x;
    for (int i = tid; i < 128 * 40 / 4; i += 128)
        ((float4*)Ws)[i] = ((const float4*)W)[i];
    __syncthreads();
    int row = blockIdx.x * 128 + tid;
    if (row >= M) return;
    const float4* a4 = (const float4*)(A + (size_t)row * 128);
    float acc[40] = {};
    for (int kq = 0; kq < 32; kq++) {
        float4 a = a4[kq];
        float av[4] = {a.x, a.y, a.z, a.w};
#pragma unroll
        for (int j = 0; j < 4; j++) {
            const float4* wr = (const float4*)(&Ws[kq * 4 + j][0]);
            float aj = av[j];
#pragma unroll
            for (int c4 = 0; c4 < 10; c4++) {
                float4 w = wr[c4];
                acc[c4 * 4 + 0] += aj * w.x;
                acc[c4 * 4 + 1] += aj * w.y;
                acc[c4 * 4 + 2] += aj * w.z;
                acc[c4 * 4 + 3] += aj * w.w;
            }
        }
    }
    float* cp = C + (size_t)row * 40;
#pragma unroll
    for (int c4 = 0; c4 < 10; c4++)
        *(float4*)(cp + c4 * 4) =
            make_float4(acc[c4 * 4], acc[c4 * 4 + 1], acc[c4 * 4 + 2], acc[c4 * 4 + 3]);
}

// ---------------------------------------------------------------------------
// Elementwise kernels
// ---------------------------------------------------------------------------
__global__ void add_emb_k(const float* __restrict__ X, const float* __restrict__ emb,
                          const int* __restrict__ nw, float* __restrict__ H0, int M) {
    int i = blockIdx.x * blockDim.x + threadIdx.x;
    if (i >= M * 32) return;
    int r = i >> 5, c4 = i & 31;
    float4 x = ((const float4*)X)[i];
    float4 e = ((const float4*)(emb + (size_t)nw[r] * NH))[c4];
    ((float4*)H0)[i] = make_float4(x.x + e.x, x.y + e.y, x.z + e.z, x.w + e.w);
}
__global__ void unpool2_k(const float* __restrict__ c2, const float* __restrict__ c1,
                          const float* __restrict__ gcn,
                          const int* __restrict__ assign0, const int* __restrict__ assign1,
                          float* __restrict__ crf) {
    int w = (blockIdx.x * blockDim.x + threadIdx.x) >> 5;
    int lane = threadIdx.x & 31;
    if (w >= N0) return;
    int a0 = assign0[w];
    int a1 = assign1[a0];
    float4 v2 = ((const float4*)(c2 + (size_t)a1 * NH))[lane];
    float4 v1 = ((const float4*)(c1 + (size_t)a0 * NH))[lane];
    float4 vg = ((const float4*)(gcn + (size_t)w * NH))[lane];
    ((float4*)(crf + (size_t)w * NH))[lane] =
        make_float4(v2.x + v1.x + vg.x, v2.y + v1.y + vg.y,
                    v2.z + v1.z + vg.z, v2.w + v1.w + vg.w);
}

// ---------------------------------------------------------------------------
// Host launch
// ---------------------------------------------------------------------------
static inline int cdiv(long long a, long long b) { return (int)((a + b - 1) / b); }

extern "C" void kernel_launch(void* const* d_in, const int* in_sizes, int n_in,
                              void* d_out, int out_size) {
    const float* x       = (const float*)d_in[0];
    const int*   A0      = (const int*)d_in[1];
    const float* A0v     = (const float*)d_in[2];
    const int*   A1      = (const int*)d_in[3];
    const float* A1v     = (const float*)d_in[4];
    const int*   A2      = (const int*)d_in[5];
    const float* A2v     = (const float*)d_in[6];
    const int*   assign0 = (const int*)d_in[7];
    const int*   assign1 = (const int*)d_in[8];
    const int*   nwgt1   = (const int*)d_in[9];
    const int*   nwgt2   = (const int*)d_in[10];
    const float* gc1_W   = (const float*)d_in[11];
    const float* gc1_b   = (const float*)d_in[12];
    const float* gc2_W   = (const float*)d_in[13];
    const float* gc2_b   = (const float*)d_in[14];
    const float* c1Wq    = (const float*)d_in[15];
    const float* c1Wk    = (const float*)d_in[16];
    const float* c1emb   = (const float*)d_in[17];
    const float* c1a     = (const float*)d_in[18];
    const float* c1b     = (const float*)d_in[19];
    const float* c2Wq    = (const float*)d_in[20];
    const float* c2Wk    = (const float*)d_in[21];
    const float* c2emb   = (const float*)d_in[22];
    const float* c2a     = (const float*)d_in[23];
    const float* c2b     = (const float*)d_in[24];

    float* out = (float*)d_out;                       // [N0, NC]
    float* gcn = out + (size_t)N0 * NC;               // [N0, NH]
    float* crf = gcn + (size_t)N0 * NH;               // [N0, NH]

    void *p_xW, *p_p1, *p_q1, *p_k1, *p_h01, *p_c1;
    void *p_p2, *p_q2, *p_k2, *p_h02, *p_c2, *p_hW2;
    void *p_cnt, *p_bs, *p_rp, *p_es, *p_ev;
    void *p_rp1, *p_ec1, *p_rp2, *p_ec2;
    cudaGetSymbolAddress(&p_xW, g_xW);   cudaGetSymbolAddress(&p_p1, g_p1);
    cudaGetSymbolAddress(&p_q1, g_q1);   cudaGetSymbolAddress(&p_k1, g_k1);
    cudaGetSymbolAddress(&p_h01, g_h01); cudaGetSymbolAddress(&p_c1, g_c1);
    cudaGetSymbolAddress(&p_p2, g_p2);   cudaGetSymbolAddress(&p_q2, g_q2);
    cudaGetSymbolAddress(&p_k2, g_k2);   cudaGetSymbolAddress(&p_h02, g_h02);
    cudaGetSymbolAddress(&p_c2, g_c2);   cudaGetSymbolAddress(&p_hW2, g_hW2);
    cudaGetSymbolAddress(&p_cnt, g_cnt); cudaGetSymbolAddress(&p_bs, g_bsum);
    cudaGetSymbolAddress(&p_rp, g_rowptr);
    cudaGetSymbolAddress(&p_es, g_esrc); cudaGetSymbolAddress(&p_ev, g_eval);
    cudaGetSymbolAddress(&p_rp1, g_rowptr1); cudaGetSymbolAddress(&p_ec1, g_ecol1);
    cudaGetSymbolAddress(&p_rp2, g_rowptr2); cudaGetSymbolAddress(&p_ec2, g_ecol2);

    float* xW  = (float*)p_xW;  float* p1 = (float*)p_p1;  float* q1 = (float*)p_q1;
    float* k1  = (float*)p_k1;  float* h01 = (float*)p_h01; float* c1 = (float*)p_c1;
    float* p2  = (float*)p_p2;  float* q2 = (float*)p_q2;  float* k2 = (float*)p_k2;
    float* h02 = (float*)p_h02; float* c2 = (float*)p_c2;  float* hW2 = (float*)p_hW2;
    int* cnt = (int*)p_cnt; int* bsum = (int*)p_bs;
    int* rowptr = (int*)p_rp; int* esrc = (int*)p_es; float* eval = (float*)p_ev;
    int* rowptr1 = (int*)p_rp1; int* ecol1 = (int*)p_ec1;
    int* rowptr2 = (int*)p_rp2; int* ecol2 = (int*)p_ec2;

    const int TB = 256;
    const int NBLK0 = cdiv(N0, 1024);   // 98
    const int NBLK1 = cdiv(N1, 1024);   // 25
    const int NBLK2 = cdiv(N2, 1024);   // 7

    // ---- Build dst-CSR of A0 ----
    cudaMemsetAsync(cnt, 0, N0 * 4);
    hist_k<<<cdiv(E0, TB), TB>>>(A0, cnt, E0);
    scan1_k<<<NBLK0, 256>>>(cnt, rowptr, bsum, N0);
    scan2_k<<<1, 128>>>(bsum, NBLK0);
    scan3_k<<<cdiv(N0, TB), TB>>>(rowptr, bsum, N0);
    cudaMemsetAsync(cnt, 0, N0 * 4);
    scatter_edges_k<<<cdiv(E0, TB), TB>>>(A0, A0 + E0, A0v, rowptr, cnt, esrc, eval, E0);

    // ---- Build dst-CSR of A1 (src only) ----
    cudaMemsetAsync(cnt, 0, N1 * 4);
    hist_k<<<cdiv(E1, TB), TB>>>(A1, cnt, E1);
    scan1_k<<<NBLK1, 256>>>(cnt, rowptr1, bsum, N1);
    scan2_k<<<1, 128>>>(bsum, NBLK1);
    scan3_k<<<cdiv(N1, TB), TB>>>(rowptr1, bsum, N1);
    cudaMemsetAsync(cnt, 0, N1 * 4);
    scatter_src_k<<<cdiv(E1, TB), TB>>>(A1, A1 + E1, rowptr1, cnt, ecol1, E1);

    // ---- Build dst-CSR of A2 (src only) ----
    cudaMemsetAsync(cnt, 0, N2 * 4);
    hist_k<<<cdiv(E2, TB), TB>>>(A2, cnt, E2);
    scan1_k<<<NBLK2, 256>>>(cnt, rowptr2, bsum, N2);
    scan2_k<<<1, 128>>>(bsum, NBLK2);
    scan3_k<<<cdiv(N2, TB), TB>>>(rowptr2, bsum, N2);
    cudaMemsetAsync(cnt, 0, N2 * 4);
    scatter_src_k<<<cdiv(E2, TB), TB>>>(A2, A2 + E2, rowptr2, cnt, ecol2, E2);

    // ---- GCN layer 1 GEMM: xW = x @ W1 ----
    {
        dim3 g(1, cdiv(N0, BM));
        gemm_nk128<<<g, 256>>>(x, gc1_W, gc1_W, xW, xW, N0);
    }

    // ---- Fused: gcn = relu(A0 @ xW + b1); p1[assign0] += gcn ----
    cudaMemsetAsync(p1, 0, (size_t)N1 * NH * 4);
    spmm_csr128_fused<<<cdiv((long long)N0 * 32, TB), TB>>>(rowptr, esrc, eval, xW,
                                                            gc1_b, gcn, assign0, p1);

    // ---- level 1 CRF (fully fused; pools into p2) ----
    {
        dim3 g(2, cdiv(N1, BM));
        gemm_nk128<<<g, 256>>>(p1, c1Wq, c1Wk, q1, k1, N1);
    }
    add_emb_k<<<cdiv((long long)N1 * 32, TB), TB>>>(p1, c1emb, nwgt1, h01, N1);
    cudaMemsetAsync(p2, 0, (size_t)N2 * NH * 4);
    crf_fused_k<<<cdiv((long long)N1 * 32, TB), TB>>>(rowptr1, ecol1, q1, k1, h01,
                                                      c1a, c1b, c1, assign1, p2, N1);

    // ---- level 2 CRF (fully fused) ----
    {
        dim3 g(2, cdiv(N2, BM));
        gemm_nk128<<<g, 256>>>(p2, c2Wq, c2Wk, q2, k2, N2);
    }
    add_emb_k<<<cdiv((long long)N2 * 32, TB), TB>>>(p2, c2emb, nwgt2, h02, N2);
    crf_fused_k<<<cdiv((long long)N2 * 32, TB), TB>>>(rowptr2, ecol2, q2, k2, h02,
                                                      c2a, c2b, c2, nullptr, nullptr, N2);

    // ---- fused unpool with skips ----
    unpool2_k<<<cdiv((long long)N0 * 32, TB), TB>>>(c2, c1, gcn, assign0, assign1, crf);

    // ---- GCN layer 2: out = A0 @ (crf @ W2) + b2 ----
    gemm_n40<<<cdiv(N0, 128), 128>>>(crf, gc2_W, hW2, N0);
    spmm_csr40<<<cdiv((long long)N0 * 32, TB), TB>>>(rowptr, esrc, eval, hW2, gc2_b, out);
}

// round 11
// speedup vs baseline: 1.3672x; 1.0594x over previous
#include <cuda_runtime.h>
#include <cuda_bf16.h>
#include <cstdio>
#include <cstdint>

// Problem constants
#define N0 100000
#define N1 25000
#define N2 6250
#define E0 1600000
#define E1 400000
#define E2 100000
#define NF 128
#define NH 128
#define NC 40
#define NBLK0 98
#define NBLK1 25
#define NBLK2 7

// ---------------------------------------------------------------------------
// Scratch (device globals — no allocation allowed)
// ---------------------------------------------------------------------------
__device__ __align__(16) float g_xW[(size_t)N0 * NH];
__device__ __align__(16) float g_p1[(size_t)N1 * NH];
__device__ __align__(16) float g_q1[(size_t)N1 * NH];
__device__ __align__(16) float g_k1[(size_t)N1 * NH];
__device__ __align__(16) float g_h01[(size_t)N1 * NH];
__device__ __align__(16) float g_c1[(size_t)N1 * NH];
__device__ __align__(16) float g_p2[(size_t)N2 * NH];
__device__ __align__(16) float g_q2[(size_t)N2 * NH];
__device__ __align__(16) float g_k2[(size_t)N2 * NH];
__device__ __align__(16) float g_h02[(size_t)N2 * NH];
__device__ __align__(16) float g_c2[(size_t)N2 * NH];
__device__ __align__(16) float g_hW2[(size_t)N0 * NC];
// CSR scratch (cnt arrays contiguous so one memset clears all three)
__device__ int   g_cntAll[N0 + N1 + N2];
__device__ int   g_bsum[192];
__device__ int   g_rowptr[N0 + 1];
__device__ int   g_esrc[E0];
__device__ float g_eval[E0];
__device__ int   g_rowptr1[N1 + 1];
__device__ int   g_ecol1[E1];
__device__ int   g_rowptr2[N2 + 1];
__device__ int   g_ecol2[E2];

// ---------------------------------------------------------------------------
// Helpers
// ---------------------------------------------------------------------------
__device__ __forceinline__ void red_add_v4(float4* addr, float a, float b, float c, float d) {
    asm volatile("red.global.add.v4.f32 [%0], {%1, %2, %3, %4};"
                 :: "l"(addr), "f"(a), "f"(b), "f"(c), "f"(d) : "memory");
}
__device__ __forceinline__ unsigned long long pack2(float lo, float hi) {
    unsigned long long r;
    asm("mov.b64 %0, {%1, %2};" : "=l"(r) : "f"(lo), "f"(hi));
    return r;
}
__device__ __forceinline__ void fma2(unsigned long long& d, unsigned long long a,
                                     unsigned long long b) {
    asm("fma.rn.f32x2 %0, %1, %2, %0;" : "+l"(d) : "l"(a), "l"(b));
}
__device__ __forceinline__ float2 unpack2(unsigned long long v) {
    float lo, hi;
    asm("mov.b64 {%0, %1}, %2;" : "=f"(lo), "=f"(hi) : "l"(v));
    return make_float2(lo, hi);
}

// ---------------------------------------------------------------------------
// Fused CSR build for all three graphs
// ---------------------------------------------------------------------------
__global__ void hist3_k(const int* __restrict__ A0, const int* __restrict__ A1,
                        const int* __restrict__ A2, int* __restrict__ cntAll) {
    int t = blockIdx.x * blockDim.x + threadIdx.x;
    if (t < E0) atomicAdd(cntAll + A0[t], 1);
    else if (t < E0 + E1) atomicAdd(cntAll + N0 + A1[t - E0], 1);
    else if (t < E0 + E1 + E2) atomicAdd(cntAll + N0 + N1 + A2[t - E0 - E1], 1);
}
__global__ void scan1m_k(const int* __restrict__ cntAll, int* __restrict__ rp0,
                         int* __restrict__ rp1, int* __restrict__ rp2,
                         int* __restrict__ bsum) {
    __shared__ int s[256];
    int b = blockIdx.x, t = threadIdx.x;
    const int* cnt; int* rowptr; int n, lb;
    if (b < NBLK0)              { cnt = cntAll;            rowptr = rp0; n = N0; lb = b; }
    else if (b < NBLK0 + NBLK1) { cnt = cntAll + N0;       rowptr = rp1; n = N1; lb = b - NBLK0; }
    else                        { cnt = cntAll + N0 + N1;  rowptr = rp2; n = N2; lb = b - NBLK0 - NBLK1; }
    int base = lb * 1024 + t * 4;
    int v0 = (base + 0 < n) ? cnt[base + 0] : 0;
    int v1 = (base + 1 < n) ? cnt[base + 1] : 0;
    int v2 = (base + 2 < n) ? cnt[base + 2] : 0;
    int v3 = (base + 3 < n) ? cnt[base + 3] : 0;
    int x0 = v0, x1 = x0 + v1, x2 = x1 + v2, x3 = x2 + v3;
    s[t] = x3;
    __syncthreads();
    for (int off = 1; off < 256; off <<= 1) {
        int val = 0;
        if (t >= off) val = s[t - off];
        __syncthreads();
        if (t >= off) s[t] += val;
        __syncthreads();
    }
    int prev = (t > 0) ? s[t - 1] : 0;
    if (base + 0 < n) rowptr[base + 1] = prev + x0;
    if (base + 1 < n) rowptr[base + 2] = prev + x1;
    if (base + 2 < n) rowptr[base + 3] = prev + x2;
    if (base + 3 < n) rowptr[base + 4] = prev + x3;
    if (t == 255) bsum[b] = s[255];
}
__global__ void scan2m_k(int* __restrict__ bsum) {
    __shared__ int s[128];
    int g = blockIdx.x, t = threadIdx.x;
    int base = (g == 0) ? 0 : ((g == 1) ? NBLK0 : NBLK0 + NBLK1);
    int nb   = (g == 0) ? NBLK0 : ((g == 1) ? NBLK1 : NBLK2);
    int v = (t < nb) ? bsum[base + t] : 0;
    s[t] = v;
    __syncthreads();
    for (int off = 1; off < 128; off <<= 1) {
        int val = 0;
        if (t >= off) val = s[t - off];
        __syncthreads();
        if (t >= off) s[t] += val;
        __syncthreads();
    }
    if (t < nb) bsum[base + t] = s[t] - v;   // exclusive
}
__global__ void scan3m_k(int* __restrict__ rp0, int* __restrict__ rp1,
                         int* __restrict__ rp2, const int* __restrict__ bsum) {
    int i = blockIdx.x * blockDim.x + threadIdx.x;
    if (i < N0) {
        if (i == 0) rp0[0] = 0;
        rp0[i + 1] += bsum[i >> 10];
    } else if (i < N0 + N1) {
        int j = i - N0;
        if (j == 0) rp1[0] = 0;
        rp1[j + 1] += bsum[NBLK0 + (j >> 10)];
    } else if (i < N0 + N1 + N2) {
        int j = i - N0 - N1;
        if (j == 0) rp2[0] = 0;
        rp2[j + 1] += bsum[NBLK0 + NBLK1 + (j >> 10)];
    }
}
// Reverse-fill scatter: consumes leftover histogram via atomicSub (no cursor memset).
__global__ void scatter3_k(const int* __restrict__ A0, const float* __restrict__ A0v,
                           const int* __restrict__ A1, const int* __restrict__ A2,
                           const int* __restrict__ rp0, const int* __restrict__ rp1,
                           const int* __restrict__ rp2, int* __restrict__ cntAll,
                           int* __restrict__ esrc, float* __restrict__ eval,
                           int* __restrict__ ecol1, int* __restrict__ ecol2) {
    int t = blockIdx.x * blockDim.x + threadIdx.x;
    if (t < E0) {
        int d = A0[t];
        int old = atomicSub(cntAll + d, 1);
        int pos = rp0[d] + old - 1;
        esrc[pos] = A0[E0 + t];
        eval[pos] = A0v[t];
    } else if (t < E0 + E1) {
        int e = t - E0;
        int d = A1[e];
        int old = atomicSub(cntAll + N0 + d, 1);
        ecol1[rp1[d] + old - 1] = A1[E1 + e];
    } else if (t < E0 + E1 + E2) {
        int e = t - E0 - E1;
        int d = A2[e];
        int old = atomicSub(cntAll + N0 + N1 + d, 1);
        ecol2[rp2[d] + old - 1] = A2[E2 + e];
    }
}

// ---------------------------------------------------------------------------
// SGEMM N=K=128, packed f32x2 FMA (dual-output launch via blockIdx.y)
// ---------------------------------------------------------------------------
#define BM 128
#define BN 128
#define BKK 16
__global__ __launch_bounds__(256, 2)
void gemm_nk128(const float* __restrict__ A,
                const float* __restrict__ Ba, const float* __restrict__ Bb,
                float* __restrict__ Ca, float* __restrict__ Cb, int M) {
    __shared__ float As[BKK][BM + 4];
    __shared__ float Bs[BKK][BN];
    const float* __restrict__ B = (blockIdx.y == 0) ? Ba : Bb;
    float* __restrict__ C = (blockIdx.y == 0) ? Ca : Cb;

    int tid = threadIdx.x;
    int row0 = blockIdx.x * BM;
    int trow = tid >> 4;
    int tcol = tid & 15;

    unsigned long long acc2[8][4] = {};
    float a_reg[8];

    for (int k0 = 0; k0 < 128; k0 += BKK) {
#pragma unroll
        for (int i = 0; i < 2; i++) {
            int idx = tid + i * 256;
            int r = idx >> 2;
            int kq = idx & 3;
            float4 v = make_float4(0.f, 0.f, 0.f, 0.f);
            int gr = row0 + r;
            if (gr < M)
                v = *(const float4*)(A + (size_t)gr * 128 + k0 + kq * 4);
            As[kq * 4 + 0][r] = v.x;
            As[kq * 4 + 1][r] = v.y;
            As[kq * 4 + 2][r] = v.z;
            As[kq * 4 + 3][r] = v.w;
        }
#pragma unroll
        for (int i = 0; i < 2; i++) {
            int idx = tid + i * 256;
            int r = idx >> 5;
            int c4 = idx & 31;
            float4 v = *(const float4*)(B + (size_t)(k0 + r) * 128 + c4 * 4);
            *(float4*)(&Bs[r][c4 * 4]) = v;
        }
        __syncthreads();
#pragma unroll
        for (int kk = 0; kk < BKK; kk++) {
            *(float4*)(a_reg)     = *(const float4*)(&As[kk][trow * 8]);
            *(float4*)(a_reg + 4) = *(const float4*)(&As[kk][trow * 8 + 4]);
            float4 bl = *(const float4*)(&Bs[kk][tcol * 8]);
            float4 bh = *(const float4*)(&Bs[kk][tcol * 8 + 4]);
            unsigned long long b2[4];
            b2[0] = pack2(bl.x, bl.y); b2[1] = pack2(bl.z, bl.w);
            b2[2] = pack2(bh.x, bh.y); b2[3] = pack2(bh.z, bh.w);
#pragma unroll
            for (int i = 0; i < 8; i++) {
                unsigned long long ad = pack2(a_reg[i], a_reg[i]);
#pragma unroll
                for (int jp = 0; jp < 4; jp++) fma2(acc2[i][jp], ad, b2[jp]);
            }
        }
        __syncthreads();
    }
#pragma unroll
    for (int i = 0; i < 8; i++) {
        int gr = row0 + trow * 8 + i;
        if (gr >= M) continue;
        float* cp = C + (size_t)gr * 128 + tcol * 8;
        float2 p0 = unpack2(acc2[i][0]), p1 = unpack2(acc2[i][1]);
        float2 p2 = unpack2(acc2[i][2]), p3 = unpack2(acc2[i][3]);
        *(float4*)(cp)     = make_float4(p0.x, p0.y, p1.x, p1.y);
        *(float4*)(cp + 4) = make_float4(p2.x, p2.y, p3.x, p3.y);
    }
}

// ---------------------------------------------------------------------------
// GEMM C[M,40] = A[M,128] @ W[128,40], packed f32x2, 2 rows per thread.
// 128 threads cover 256 rows per block.
// ---------------------------------------------------------------------------
__global__ __launch_bounds__(128)
void gemm_n40(const float* __restrict__ A, const float* __restrict__ W,
              float* __restrict__ C, int M) {
    __shared__ unsigned long long Ws2[128][20];
    int tid = threadIdx.x;
    for (int i = tid; i < 128 * 20; i += 128) {
        int k = i / 20, p = i % 20;
        Ws2[k][p] = pack2(W[k * 40 + 2 * p], W[k * 40 + 2 * p + 1]);
    }
    __syncthreads();
    int row0 = blockIdx.x * 256 + tid;
    int row1 = row0 + 128;
    bool ok0 = row0 < M, ok1 = row1 < M;
    if (!ok0) return;
    const float4* a4_0 = (const float4*)(A + (size_t)row0 * 128);
    const float4* a4_1 = (const float4*)(A + (size_t)row1 * 128);
    unsigned long long acc0[20] = {}, acc1[20] = {};
    for (int kq = 0; kq < 32; kq++) {
        float4 va = a4_0[kq];
        float4 vb = ok1 ? a4_1[kq] : make_float4(0, 0, 0, 0);
        float av[4] = {va.x, va.y, va.z, va.w};
        float bv[4] = {vb.x, vb.y, vb.z, vb.w};
#pragma unroll
        for (int j = 0; j < 4; j++) {
            unsigned long long a0d = pack2(av[j], av[j]);
            unsigned long long a1d = pack2(bv[j], bv[j]);
            const unsigned long long* wr = &Ws2[kq * 4 + j][0];
#pragma unroll
            for (int p = 0; p < 20; p++) {
                unsigned long long w = wr[p];
                fma2(acc0[p], a0d, w);
                fma2(acc1[p], a1d, w);
            }
        }
    }
    float* cp0 = C + (size_t)row0 * 40;
#pragma unroll
    for (int p = 0; p < 10; p++) {
        float2 lo = unpack2(acc0[2 * p]), hi = unpack2(acc0[2 * p + 1]);
        *(float4*)(cp0 + 4 * p) = make_float4(lo.x, lo.y, hi.x, hi.y);
    }
    if (ok1) {
        float* cp1 = C + (size_t)row1 * 40;
#pragma unroll
        for (int p = 0; p < 10; p++) {
            float2 lo = unpack2(acc1[2 * p]), hi = unpack2(acc1[2 * p + 1]);
            *(float4*)(cp1 + 4 * p) = make_float4(lo.x, lo.y, hi.x, hi.y);
        }
    }
}

// ---------------------------------------------------------------------------
// CSR SpMM (128 feats) fused, MLP-8 batched gathers:
// gcn = relu(A0 @ X + b); p1[assign0] += gcn
// ---------------------------------------------------------------------------
__global__ __launch_bounds__(256)
void spmm_csr128_fused(const int* __restrict__ rowptr, const int* __restrict__ esrc,
                       const float* __restrict__ eval, const float* __restrict__ X,
                       const float* __restrict__ bias, float* __restrict__ gcn,
                       const int* __restrict__ assign0, float* __restrict__ p1) {
    int w = (blockIdx.x * blockDim.x + threadIdx.x) >> 5;
    int lane = threadIdx.x & 31;
    if (w >= N0) return;
    int s = rowptr[w], e = rowptr[w + 1];
    float4 acc = ((const float4*)bias)[lane];
    const float4* X4 = (const float4*)X;

    for (int i = s; i < e; i += 8) {
        int nb = e - i; if (nb > 8) nb = 8;
        int   src_l = (lane < nb) ? esrc[i + lane] : 0;
        float val_l = (lane < nb) ? eval[i + lane] : 0.f;
        float4 a[8];
#pragma unroll
        for (int j = 0; j < 8; j++) {
            int s0 = __shfl_sync(0xFFFFFFFFu, src_l, j);
            if (j < nb) a[j] = X4[(size_t)s0 * 32 + lane];
        }
#pragma unroll
        for (int j = 0; j < 8; j++) {
            float v0 = __shfl_sync(0xFFFFFFFFu, val_l, j);
            if (j < nb) {
                acc.x += v0 * a[j].x; acc.y += v0 * a[j].y;
                acc.z += v0 * a[j].z; acc.w += v0 * a[j].w;
            }
        }
    }
    acc.x = fmaxf(acc.x, 0.f); acc.y = fmaxf(acc.y, 0.f);
    acc.z = fmaxf(acc.z, 0.f); acc.w = fmaxf(acc.w, 0.f);
    ((float4*)(gcn + (size_t)w * NH))[lane] = acc;
    int d = assign0[w];
    red_add_v4(((float4*)(p1 + (size_t)d * NH)) + lane, acc.x, acc.y, acc.z, acc.w);
}

// ---------------------------------------------------------------------------
// CSR SpMM (40 feats), MLP-8 batched: out = A0 @ X + b2
// ---------------------------------------------------------------------------
__global__ __launch_bounds__(256)
void spmm_csr40(const int* __restrict__ rowptr, const int* __restrict__ esrc,
                const float* __restrict__ eval, const float* __restrict__ X,
                const float* __restrict__ bias, float* __restrict__ out) {
    int w = (blockIdx.x * blockDim.x + threadIdx.x) >> 5;
    int lane = threadIdx.x & 31;
    if (w >= N0) return;
    int s = rowptr[w], e = rowptr[w + 1];
    bool act = lane < 10;
    float4 acc = act ? ((const float4*)bias)[lane] : make_float4(0, 0, 0, 0);
    const float4* X4 = (const float4*)X;

    for (int i = s; i < e; i += 8) {
        int nb = e - i; if (nb > 8) nb = 8;
        int   src_l = (lane < nb) ? esrc[i + lane] : 0;
        float val_l = (lane < nb) ? eval[i + lane] : 0.f;
        float4 a[8];
#pragma unroll
        for (int j = 0; j < 8; j++) {
            int s0 = __shfl_sync(0xFFFFFFFFu, src_l, j);
            if (j < nb && act) a[j] = X4[(size_t)s0 * 10 + lane];
        }
#pragma unroll
        for (int j = 0; j < 8; j++) {
            float v0 = __shfl_sync(0xFFFFFFFFu, val_l, j);
            if (j < nb && act) {
                acc.x += v0 * a[j].x; acc.y += v0 * a[j].y;
                acc.z += v0 * a[j].z; acc.w += v0 * a[j].w;
            }
        }
    }
    if (act) ((float4*)(out + (size_t)w * NC))[lane] = acc;
}

// ---------------------------------------------------------------------------
// Fused CRF: one warp per dst row, online softmax over CSR edges.
// ---------------------------------------------------------------------------
__global__ __launch_bounds__(256)
void crf_fused_k(const int* __restrict__ rowptr, const int* __restrict__ ecol,
                 const float* __restrict__ Q, const float* __restrict__ Km,
                 const float* __restrict__ H0,
                 const float* __restrict__ pa, const float* __restrict__ pb,
                 float* __restrict__ OUT, const int* __restrict__ assign,
                 float* __restrict__ P, int n) {
    int w = (blockIdx.x * blockDim.x + threadIdx.x) >> 5;
    int lane = threadIdx.x & 31;
    if (w >= n) return;
    int s = rowptr[w], e = rowptr[w + 1];
    const float4* K4 = (const float4*)Km;
    const float4* H4 = (const float4*)H0;

    float4 q4 = ((const float4*)(Q + (size_t)w * NH))[lane];

    float m = -3.4e38f, z = 0.f;
    float4 macc = make_float4(0.f, 0.f, 0.f, 0.f);

    for (int i = s; i < e; i += 8) {
        int nb = e - i; if (nb > 8) nb = 8;
        int src_l = (lane < nb) ? ecol[i + lane] : 0;
        float4 buf[8];
#pragma unroll
        for (int j = 0; j < 8; j++) {
            int s0 = __shfl_sync(0xFFFFFFFFu, src_l, j);
            if (j < nb) buf[j] = K4[(size_t)s0 * 32 + lane];
        }
        float lj[8];
#pragma unroll
        for (int j = 0; j < 8; j++) {
            if (j < nb) {
                float d = q4.x * buf[j].x + q4.y * buf[j].y +
                          q4.z * buf[j].z + q4.w * buf[j].w;
#pragma unroll
                for (int o = 16; o; o >>= 1) d += __shfl_xor_sync(0xFFFFFFFFu, d, o);
                lj[j] = d * 0.08838834764831845f;   // 1/sqrt(128)
            }
        }
        float bm = -3.4e38f;
#pragma unroll
        for (int j = 0; j < 8; j++) if (j < nb) bm = fmaxf(bm, lj[j]);
        float nm = fmaxf(m, bm);
        float sc = __expf(m - nm);
        z *= sc;
        macc.x *= sc; macc.y *= sc; macc.z *= sc; macc.w *= sc;
        m = nm;
#pragma unroll
        for (int j = 0; j < 8; j++) {
            int s0 = __shfl_sync(0xFFFFFFFFu, src_l, j);
            if (j < nb) buf[j] = H4[(size_t)s0 * 32 + lane];
        }
#pragma unroll
        for (int j = 0; j < 8; j++) {
            if (j < nb) {
                float ej = __expf(lj[j] - m);
                z += ej;
                macc.x += ej * buf[j].x; macc.y += ej * buf[j].y;
                macc.z += ej * buf[j].z; macc.w += ej * buf[j].w;
            }
        }
    }
    float coef = 1.f / (z + 1e-16f);
    float a = *pa, b = *pb, inv = 1.f / (a + b);
    float4 h0d = H4[(size_t)w * 32 + lane];
    float4 c = make_float4((a * h0d.x + b * macc.x * coef) * inv,
                           (a * h0d.y + b * macc.y * coef) * inv,
                           (a * h0d.z + b * macc.z * coef) * inv,
                           (a * h0d.w + b * macc.w * coef) * inv);
    ((float4*)(OUT + (size_t)w * NH))[lane] = c;
    if (P) {
        int d = assign[w];
        red_add_v4(((float4*)(P + (size_t)d * NH)) + lane, c.x, c.y, c.z, c.w);
    }
}

// ---------------------------------------------------------------------------
// Elementwise kernels
// ---------------------------------------------------------------------------
__global__ void add_emb_k(const float* __restrict__ X, const float* __restrict__ emb,
                          const int* __restrict__ nw, float* __restrict__ H0, int M) {
    int i = blockIdx.x * blockDim.x + threadIdx.x;
    if (i >= M * 32) return;
    int r = i >> 5, c4 = i & 31;
    float4 x = ((const float4*)X)[i];
    float4 e = ((const float4*)(emb + (size_t)nw[r] * NH))[c4];
    ((float4*)H0)[i] = make_float4(x.x + e.x, x.y + e.y, x.z + e.z, x.w + e.w);
}
__global__ void unpool2_k(const float* __restrict__ c2, const float* __restrict__ c1,
                          const float* __restrict__ gcn,
                          const int* __restrict__ assign0, const int* __restrict__ assign1,
                          float* __restrict__ crf) {
    int w = (blockIdx.x * blockDim.x + threadIdx.x) >> 5;
    int lane = threadIdx.x & 31;
    if (w >= N0) return;
    int a0 = assign0[w];
    int a1 = assign1[a0];
    float4 v2 = ((const float4*)(c2 + (size_t)a1 * NH))[lane];
    float4 v1 = ((const float4*)(c1 + (size_t)a0 * NH))[lane];
    float4 vg = ((const float4*)(gcn + (size_t)w * NH))[lane];
    ((float4*)(crf + (size_t)w * NH))[lane] =
        make_float4(v2.x + v1.x + vg.x, v2.y + v1.y + vg.y,
                    v2.z + v1.z + vg.z, v2.w + v1.w + vg.w);
}

// ---------------------------------------------------------------------------
// Host launch
// ---------------------------------------------------------------------------
static inline int cdiv(long long a, long long b) { return (int)((a + b - 1) / b); }

extern "C" void kernel_launch(void* const* d_in, const int* in_sizes, int n_in,
                              void* d_out, int out_size) {
    const float* x       = (const float*)d_in[0];
    const int*   A0      = (const int*)d_in[1];
    const float* A0v     = (const float*)d_in[2];
    const int*   A1      = (const int*)d_in[3];
    const float* A1v     = (const float*)d_in[4];
    const int*   A2      = (const int*)d_in[5];
    const float* A2v     = (const float*)d_in[6];
    const int*   assign0 = (const int*)d_in[7];
    const int*   assign1 = (const int*)d_in[8];
    const int*   nwgt1   = (const int*)d_in[9];
    const int*   nwgt2   = (const int*)d_in[10];
    const float* gc1_W   = (const float*)d_in[11];
    const float* gc1_b   = (const float*)d_in[12];
    const float* gc2_W   = (const float*)d_in[13];
    const float* gc2_b   = (const float*)d_in[14];
    const float* c1Wq    = (const float*)d_in[15];
    const float* c1Wk    = (const float*)d_in[16];
    const float* c1emb   = (const float*)d_in[17];
    const float* c1a     = (const float*)d_in[18];
    const float* c1b     = (const float*)d_in[19];
    const float* c2Wq    = (const float*)d_in[20];
    const float* c2Wk    = (const float*)d_in[21];
    const float* c2emb   = (const float*)d_in[22];
    const float* c2a     = (const float*)d_in[23];
    const float* c2b     = (const float*)d_in[24];

    float* out = (float*)d_out;                       // [N0, NC]
    float* gcn = out + (size_t)N0 * NC;               // [N0, NH]
    float* crf = gcn + (size_t)N0 * NH;               // [N0, NH]

    void *p_xW, *p_p1, *p_q1, *p_k1, *p_h01, *p_c1;
    void *p_p2, *p_q2, *p_k2, *p_h02, *p_c2, *p_hW2;
    void *p_cnt, *p_bs, *p_rp, *p_es, *p_ev;
    void *p_rp1, *p_ec1, *p_rp2, *p_ec2;
    cudaGetSymbolAddress(&p_xW, g_xW);   cudaGetSymbolAddress(&p_p1, g_p1);
    cudaGetSymbolAddress(&p_q1, g_q1);   cudaGetSymbolAddress(&p_k1, g_k1);
    cudaGetSymbolAddress(&p_h01, g_h01); cudaGetSymbolAddress(&p_c1, g_c1);
    cudaGetSymbolAddress(&p_p2, g_p2);   cudaGetSymbolAddress(&p_q2, g_q2);
    cudaGetSymbolAddress(&p_k2, g_k2);   cudaGetSymbolAddress(&p_h02, g_h02);
    cudaGetSymbolAddress(&p_c2, g_c2);   cudaGetSymbolAddress(&p_hW2, g_hW2);
    cudaGetSymbolAddress(&p_cnt, g_cntAll); cudaGetSymbolAddress(&p_bs, g_bsum);
    cudaGetSymbolAddress(&p_rp, g_rowptr);
    cudaGetSymbolAddress(&p_es, g_esrc); cudaGetSymbolAddress(&p_ev, g_eval);
    cudaGetSymbolAddress(&p_rp1, g_rowptr1); cudaGetSymbolAddress(&p_ec1, g_ecol1);
    cudaGetSymbolAddress(&p_rp2, g_rowptr2); cudaGetSymbolAddress(&p_ec2, g_ecol2);

    float* xW  = (float*)p_xW;  float* p1 = (float*)p_p1;  float* q1 = (float*)p_q1;
    float* k1  = (float*)p_k1;  float* h01 = (float*)p_h01; float* c1 = (float*)p_c1;
    float* p2  = (float*)p_p2;  float* q2 = (float*)p_q2;  float* k2 = (float*)p_k2;
    float* h02 = (float*)p_h02; float* c2 = (float*)p_c2;  float* hW2 = (float*)p_hW2;
    int* cntAll = (int*)p_cnt;  int* bsum = (int*)p_bs;
    int* rowptr = (int*)p_rp;   int* esrc = (int*)p_es;    float* eval = (float*)p_ev;
    int* rowptr1 = (int*)p_rp1; int* ecol1 = (int*)p_ec1;
    int* rowptr2 = (int*)p_rp2; int* ecol2 = (int*)p_ec2;

    const int TB = 256;
    const long long ETOT = (long long)E0 + E1 + E2;
    const int NTOT = N0 + N1 + N2;

    // ---- Fused CSR build for A0/A1/A2 ----
    cudaMemsetAsync(cntAll, 0, (size_t)NTOT * 4);
    hist3_k<<<cdiv(ETOT, TB), TB>>>(A0, A1, A2, cntAll);
    scan1m_k<<<NBLK0 + NBLK1 + NBLK2, 256>>>(cntAll, rowptr, rowptr1, rowptr2, bsum);
    scan2m_k<<<3, 128>>>(bsum);
    scan3m_k<<<cdiv(NTOT, TB), TB>>>(rowptr, rowptr1, rowptr2, bsum);
    scatter3_k<<<cdiv(ETOT, TB), TB>>>(A0, A0v, A1, A2, rowptr, rowptr1, rowptr2,
                                       cntAll, esrc, eval, ecol1, ecol2);

    // ---- GCN layer 1 GEMM: xW = x @ W1 ----
    gemm_nk128<<<dim3(cdiv(N0, BM), 1), 256>>>(x, gc1_W, gc1_W, xW, xW, N0);

    // ---- Fused: gcn = relu(A0 @ xW + b1); p1[assign0] += gcn ----
    cudaMemsetAsync(p1, 0, (size_t)N1 * NH * 4);
    spmm_csr128_fused<<<cdiv((long long)N0 * 32, TB), TB>>>(rowptr, esrc, eval, xW,
                                                            gc1_b, gcn, assign0, p1);

    // ---- level 1 CRF ----
    gemm_nk128<<<dim3(cdiv(N1, BM), 2), 256>>>(p1, c1Wq, c1Wk, q1, k1, N1);
    add_emb_k<<<cdiv((long long)N1 * 32, TB), TB>>>(p1, c1emb, nwgt1, h01, N1);
    cudaMemsetAsync(p2, 0, (size_t)N2 * NH * 4);
    crf_fused_k<<<cdiv((long long)N1 * 32, TB), TB>>>(rowptr1, ecol1, q1, k1, h01,
                                                      c1a, c1b, c1, assign1, p2, N1);

    // ---- level 2 CRF ----
    gemm_nk128<<<dim3(cdiv(N2, BM), 2), 256>>>(p2, c2Wq, c2Wk, q2, k2, N2);
    add_emb_k<<<cdiv((long long)N2 * 32, TB), TB>>>(p2, c2emb, nwgt2, h02, N2);
    crf_fused_k<<<cdiv((long long)N2 * 32, TB), TB>>>(rowptr2, ecol2, q2, k2, h02,
                                                      c2a, c2b, c2, nullptr, nullptr, N2);

    // ---- fused unpool with skips ----
    unpool2_k<<<cdiv((long long)N0 * 32, TB), TB>>>(c2, c1, gcn, assign0, assign1, crf);

    // ---- GCN layer 2: out = A0 @ (crf @ W2) + b2 ----
    gemm_n40<<<cdiv(N0, 256), 128>>>(crf, gc2_W, hW2, N0);
    spmm_csr40<<<cdiv((long long)N0 * 32, TB), TB>>>(rowptr, esrc, eval, hW2, gc2_b, out);
}

// round 12
// speedup vs baseline: 1.5568x; 1.1387x over previous
#include <cuda_runtime.h>
#include <cuda_bf16.h>
#include <cstdio>
#include <cstdint>

// Problem constants
#define N0 100000
#define N1 25000
#define N2 6250
#define E0 1600000
#define E1 400000
#define E2 100000
#define NF 128
#define NH 128
#define NC 40
#define NBLK0 98
#define NBLK1 25
#define NBLK2 7

// ---------------------------------------------------------------------------
// Scratch (device globals — no allocation allowed)
// ---------------------------------------------------------------------------
__device__ __align__(16) float g_xW[(size_t)N0 * NH];
__device__ __align__(16) float g_p1[(size_t)N1 * NH];
__device__ __align__(16) float g_q1[(size_t)N1 * NH];
__device__ __align__(16) float g_k1[(size_t)N1 * NH];
__device__ __align__(16) float g_h01[(size_t)N1 * NH];
__device__ __align__(16) float g_c1[(size_t)N1 * NH];
__device__ __align__(16) float g_p2[(size_t)N2 * NH];
__device__ __align__(16) float g_q2[(size_t)N2 * NH];
__device__ __align__(16) float g_k2[(size_t)N2 * NH];
__device__ __align__(16) float g_h02[(size_t)N2 * NH];
__device__ __align__(16) float g_c2[(size_t)N2 * NH];
__device__ __align__(16) float g_hW2[(size_t)N0 * NC];
__device__ __align__(16) float g_Wtf[5 * 128 * 128];    // tf32-converted weights
// CSR scratch (cnt arrays contiguous so one memset clears all three)
__device__ int   g_cntAll[N0 + N1 + N2];
__device__ int   g_bsum[192];
__device__ int   g_rowptr[N0 + 1];
__device__ int   g_esrc[E0];
__device__ float g_eval[E0];
__device__ int   g_rowptr1[N1 + 1];
__device__ int   g_ecol1[E1];
__device__ int   g_rowptr2[N2 + 1];
__device__ int   g_ecol2[E2];

// ---------------------------------------------------------------------------
// Helpers
// ---------------------------------------------------------------------------
__device__ __forceinline__ void red_add_v4(float4* addr, float a, float b, float c, float d) {
    asm volatile("red.global.add.v4.f32 [%0], {%1, %2, %3, %4};"
                 :: "l"(addr), "f"(a), "f"(b), "f"(c), "f"(d) : "memory");
}
__device__ __forceinline__ unsigned long long pack2(float lo, float hi) {
    unsigned long long r;
    asm("mov.b64 %0, {%1, %2};" : "=l"(r) : "f"(lo), "f"(hi));
    return r;
}
__device__ __forceinline__ void fma2(unsigned long long& d, unsigned long long a,
                                     unsigned long long b) {
    asm("fma.rn.f32x2 %0, %1, %2, %0;" : "+l"(d) : "l"(a), "l"(b));
}
__device__ __forceinline__ float2 unpack2(unsigned long long v) {
    float lo, hi;
    asm("mov.b64 {%0, %1}, %2;" : "=f"(lo), "=f"(hi) : "l"(v));
    return make_float2(lo, hi);
}
__device__ __forceinline__ float to_tf32(float x) {
    float r;
    asm("cvt.rna.tf32.f32 %0, %1;" : "=f"(r) : "f"(x));
    return r;
}
#define MMA_TF32(c, a, b)                                                     \
    asm volatile("mma.sync.aligned.m16n8k8.row.col.f32.tf32.tf32.f32 "        \
                 "{%0,%1,%2,%3}, {%4,%5,%6,%7}, {%8,%9}, {%0,%1,%2,%3};"      \
                 : "+f"((c)[0]), "+f"((c)[1]), "+f"((c)[2]), "+f"((c)[3])     \
                 : "r"((a)[0]), "r"((a)[1]), "r"((a)[2]), "r"((a)[3]),        \
                   "r"((b)[0]), "r"((b)[1]))

// ---------------------------------------------------------------------------
// Prep: convert 5 weight matrices [128,128] to tf32 (rna) once.
// ---------------------------------------------------------------------------
__global__ void prep_tf32_k(const float* __restrict__ w0, const float* __restrict__ w1,
                            const float* __restrict__ w2, const float* __restrict__ w3,
                            const float* __restrict__ w4, float* __restrict__ out) {
    int t = blockIdx.x * blockDim.x + threadIdx.x;   // 0 .. 5*16384-1
    if (t >= 5 * 16384) return;
    int sel = t >> 14, i = t & 16383;
    const float* w = (sel == 0) ? w0 : (sel == 1) ? w1 : (sel == 2) ? w2
                                     : (sel == 3) ? w3 : w4;
    out[t] = to_tf32(w[i]);
}

// ---------------------------------------------------------------------------
// Fused CSR build for all three graphs
// ---------------------------------------------------------------------------
__global__ void hist3_k(const int* __restrict__ A0, const int* __restrict__ A1,
                        const int* __restrict__ A2, int* __restrict__ cntAll) {
    int t = blockIdx.x * blockDim.x + threadIdx.x;
    if (t < E0) atomicAdd(cntAll + A0[t], 1);
    else if (t < E0 + E1) atomicAdd(cntAll + N0 + A1[t - E0], 1);
    else if (t < E0 + E1 + E2) atomicAdd(cntAll + N0 + N1 + A2[t - E0 - E1], 1);
}
__global__ void scan1m_k(const int* __restrict__ cntAll, int* __restrict__ rp0,
                         int* __restrict__ rp1, int* __restrict__ rp2,
                         int* __restrict__ bsum) {
    __shared__ int s[256];
    int b = blockIdx.x, t = threadIdx.x;
    const int* cnt; int* rowptr; int n, lb;
    if (b < NBLK0)              { cnt = cntAll;            rowptr = rp0; n = N0; lb = b; }
    else if (b < NBLK0 + NBLK1) { cnt = cntAll + N0;       rowptr = rp1; n = N1; lb = b - NBLK0; }
    else                        { cnt = cntAll + N0 + N1;  rowptr = rp2; n = N2; lb = b - NBLK0 - NBLK1; }
    int base = lb * 1024 + t * 4;
    int v0 = (base + 0 < n) ? cnt[base + 0] : 0;
    int v1 = (base + 1 < n) ? cnt[base + 1] : 0;
    int v2 = (base + 2 < n) ? cnt[base + 2] : 0;
    int v3 = (base + 3 < n) ? cnt[base + 3] : 0;
    int x0 = v0, x1 = x0 + v1, x2 = x1 + v2, x3 = x2 + v3;
    s[t] = x3;
    __syncthreads();
    for (int off = 1; off < 256; off <<= 1) {
        int val = 0;
        if (t >= off) val = s[t - off];
        __syncthreads();
        if (t >= off) s[t] += val;
        __syncthreads();
    }
    int prev = (t > 0) ? s[t - 1] : 0;
    if (base + 0 < n) rowptr[base + 1] = prev + x0;
    if (base + 1 < n) rowptr[base + 2] = prev + x1;
    if (base + 2 < n) rowptr[base + 3] = prev + x2;
    if (base + 3 < n) rowptr[base + 4] = prev + x3;
    if (t == 255) bsum[b] = s[255];
}
__global__ void scan2m_k(int* __restrict__ bsum) {
    __shared__ int s[128];
    int g = blockIdx.x, t = threadIdx.x;
    int base = (g == 0) ? 0 : ((g == 1) ? NBLK0 : NBLK0 + NBLK1);
    int nb   = (g == 0) ? NBLK0 : ((g == 1) ? NBLK1 : NBLK2);
    int v = (t < nb) ? bsum[base + t] : 0;
    s[t] = v;
    __syncthreads();
    for (int off = 1; off < 128; off <<= 1) {
        int val = 0;
        if (t >= off) val = s[t - off];
        __syncthreads();
        if (t >= off) s[t] += val;
        __syncthreads();
    }
    if (t < nb) bsum[base + t] = s[t] - v;   // exclusive
}
__global__ void scan3m_k(int* __restrict__ rp0, int* __restrict__ rp1,
                         int* __restrict__ rp2, const int* __restrict__ bsum) {
    int i = blockIdx.x * blockDim.x + threadIdx.x;
    if (i < N0) {
        if (i == 0) rp0[0] = 0;
        rp0[i + 1] += bsum[i >> 10];
    } else if (i < N0 + N1) {
        int j = i - N0;
        if (j == 0) rp1[0] = 0;
        rp1[j + 1] += bsum[NBLK0 + (j >> 10)];
    } else if (i < N0 + N1 + N2) {
        int j = i - N0 - N1;
        if (j == 0) rp2[0] = 0;
        rp2[j + 1] += bsum[NBLK0 + NBLK1 + (j >> 10)];
    }
}
// Reverse-fill scatter: consumes leftover histogram via atomicSub (no cursor memset).
__global__ void scatter3_k(const int* __restrict__ A0, const float* __restrict__ A0v,
                           const int* __restrict__ A1, const int* __restrict__ A2,
                           const int* __restrict__ rp0, const int* __restrict__ rp1,
                           const int* __restrict__ rp2, int* __restrict__ cntAll,
                           int* __restrict__ esrc, float* __restrict__ eval,
                           int* __restrict__ ecol1, int* __restrict__ ecol2) {
    int t = blockIdx.x * blockDim.x + threadIdx.x;
    if (t < E0) {
        int d = A0[t];
        int old = atomicSub(cntAll + d, 1);
        int pos = rp0[d] + old - 1;
        esrc[pos] = A0[E0 + t];
        eval[pos] = A0v[t];
    } else if (t < E0 + E1) {
        int e = t - E0;
        int d = A1[e];
        int old = atomicSub(cntAll + N0 + d, 1);
        ecol1[rp1[d] + old - 1] = A1[E1 + e];
    } else if (t < E0 + E1 + E2) {
        int e = t - E0 - E1;
        int d = A2[e];
        int old = atomicSub(cntAll + N0 + N1 + d, 1);
        ecol2[rp2[d] + old - 1] = A2[E2 + e];
    }
}

// ---------------------------------------------------------------------------
// HMMA tf32 GEMM: C[M,128] = A[M,128] @ W[128,128]   (W pre-converted tf32)
// Block tile 128x128, 8 warps as 2(m) x 4(n), warp tile 64x32 = 4x4 m16n8k8.
// blockIdx.y selects (B0,C0) vs (B1,C1) for paired Q/K projections.
// ---------------------------------------------------------------------------
__global__ __launch_bounds__(256, 2)
void gemm_mma128(const float* __restrict__ A,
                 const float* __restrict__ B0w, const float* __restrict__ B1w,
                 float* __restrict__ C0, float* __restrict__ C1, int M) {
    __shared__ __align__(16) float As[128][20];   // [m][k] pad->conflict-free frags
    __shared__ __align__(16) float Bs[16][136];   // [k][n] pad->conflict-free frags
    const float* __restrict__ B = blockIdx.y ? B1w : B0w;
    float* __restrict__ C = blockIdx.y ? C1 : C0;

    int tid = threadIdx.x;
    int wid = tid >> 5, lane = tid & 31;
    int wm = wid >> 2;          // 0..1  (64 rows each)
    int wn = wid & 3;           // 0..3  (32 cols each)
    int g = lane >> 2;          // 0..7
    int a4 = lane & 3;          // 0..3
    int row0 = blockIdx.x * 128;

    float acc[4][4][4] = {};    // [m-atom][n-atom][reg]

    for (int st = 0; st < 8; st++) {
        int k0 = st * 16;
        // Stage A: 128 rows x 16 k (coalesced float4 loads, tf32 convert)
#pragma unroll
        for (int it = 0; it < 2; it++) {
            int idx = tid + it * 256;      // 0..511
            int m = idx >> 2, q = idx & 3;
            float4 v = make_float4(0.f, 0.f, 0.f, 0.f);
            if (row0 + m < M)
                v = *(const float4*)(A + (size_t)(row0 + m) * 128 + k0 + q * 4);
            v.x = to_tf32(v.x); v.y = to_tf32(v.y);
            v.z = to_tf32(v.z); v.w = to_tf32(v.w);
            *(float4*)&As[m][q * 4] = v;
        }
        // Stage B: 16 k x 128 n (already tf32)
#pragma unroll
        for (int it = 0; it < 2; it++) {
            int idx = tid + it * 256;
            int k = idx >> 5, c = idx & 31;
            *(float4*)&Bs[k][c * 4] = *(const float4*)(B + (size_t)(k0 + k) * 128 + c * 4);
        }
        __syncthreads();
#pragma unroll
        for (int kl0 = 0; kl0 < 16; kl0 += 8) {
            int kc = kl0 + a4;
            uint32_t af[4][4];
#pragma unroll
            for (int i = 0; i < 4; i++) {
                int r = wm * 64 + i * 16 + g;
                af[i][0] = __float_as_uint(As[r][kc]);
                af[i][1] = __float_as_uint(As[r + 8][kc]);
                af[i][2] = __float_as_uint(As[r][kc + 4]);
                af[i][3] = __float_as_uint(As[r + 8][kc + 4]);
            }
            uint32_t bf[4][2];
#pragma unroll
            for (int j = 0; j < 4; j++) {
                int n = wn * 32 + j * 8 + g;
                bf[j][0] = __float_as_uint(Bs[kc][n]);
                bf[j][1] = __float_as_uint(Bs[kc + 4][n]);
            }
#pragma unroll
            for (int i = 0; i < 4; i++)
#pragma unroll
                for (int j = 0; j < 4; j++)
                    MMA_TF32(acc[i][j], af[i], bf[j]);
        }
        __syncthreads();
    }
    // Epilogue
#pragma unroll
    for (int i = 0; i < 4; i++) {
        int r = row0 + wm * 64 + i * 16 + g;
#pragma unroll
        for (int j = 0; j < 4; j++) {
            int cn = wn * 32 + j * 8 + 2 * a4;
            if (r < M)
                *(float2*)(C + (size_t)r * 128 + cn) = make_float2(acc[i][j][0], acc[i][j][1]);
            if (r + 8 < M)
                *(float2*)(C + (size_t)(r + 8) * 128 + cn) = make_float2(acc[i][j][2], acc[i][j][3]);
        }
    }
}

// ---------------------------------------------------------------------------
// GEMM C[M,40] = A[M,128] @ W[128,40], packed f32x2, 2 rows per thread.
// ---------------------------------------------------------------------------
__global__ __launch_bounds__(128)
void gemm_n40(const float* __restrict__ A, const float* __restrict__ W,
              float* __restrict__ C, int M) {
    __shared__ unsigned long long Ws2[128][20];
    int tid = threadIdx.x;
    for (int i = tid; i < 128 * 20; i += 128) {
        int k = i / 20, p = i % 20;
        Ws2[k][p] = pack2(W[k * 40 + 2 * p], W[k * 40 + 2 * p + 1]);
    }
    __syncthreads();
    int row0 = blockIdx.x * 256 + tid;
    int row1 = row0 + 128;
    bool ok0 = row0 < M, ok1 = row1 < M;
    if (!ok0) return;
    const float4* a4_0 = (const float4*)(A + (size_t)row0 * 128);
    const float4* a4_1 = (const float4*)(A + (size_t)row1 * 128);
    unsigned long long acc0[20] = {}, acc1[20] = {};
    for (int kq = 0; kq < 32; kq++) {
        float4 va = a4_0[kq];
        float4 vb = ok1 ? a4_1[kq] : make_float4(0, 0, 0, 0);
        float av[4] = {va.x, va.y, va.z, va.w};
        float bv[4] = {vb.x, vb.y, vb.z, vb.w};
#pragma unroll
        for (int j = 0; j < 4; j++) {
            unsigned long long a0d = pack2(av[j], av[j]);
            unsigned long long a1d = pack2(bv[j], bv[j]);
            const unsigned long long* wr = &Ws2[kq * 4 + j][0];
#pragma unroll
            for (int p = 0; p < 20; p++) {
                unsigned long long w = wr[p];
                fma2(acc0[p], a0d, w);
                fma2(acc1[p], a1d, w);
            }
        }
    }
    float* cp0 = C + (size_t)row0 * 40;
#pragma unroll
    for (int p = 0; p < 10; p++) {
        float2 lo = unpack2(acc0[2 * p]), hi = unpack2(acc0[2 * p + 1]);
        *(float4*)(cp0 + 4 * p) = make_float4(lo.x, lo.y, hi.x, hi.y);
    }
    if (ok1) {
        float* cp1 = C + (size_t)row1 * 40;
#pragma unroll
        for (int p = 0; p < 10; p++) {
            float2 lo = unpack2(acc1[2 * p]), hi = unpack2(acc1[2 * p + 1]);
            *(float4*)(cp1 + 4 * p) = make_float4(lo.x, lo.y, hi.x, hi.y);
        }
    }
}

// ---------------------------------------------------------------------------
// CSR SpMM (128 feats) fused, MLP-8 batched gathers:
// gcn = relu(A0 @ X + b); p1[assign0] += gcn
// ---------------------------------------------------------------------------
__global__ __launch_bounds__(256)
void spmm_csr128_fused(const int* __restrict__ rowptr, const int* __restrict__ esrc,
                       const float* __restrict__ eval, const float* __restrict__ X,
                       const float* __restrict__ bias, float* __restrict__ gcn,
                       const int* __restrict__ assign0, float* __restrict__ p1) {
    int w = (blockIdx.x * blockDim.x + threadIdx.x) >> 5;
    int lane = threadIdx.x & 31;
    if (w >= N0) return;
    int s = rowptr[w], e = rowptr[w + 1];
    float4 acc = ((const float4*)bias)[lane];
    const float4* X4 = (const float4*)X;

    for (int i = s; i < e; i += 8) {
        int nb = e - i; if (nb > 8) nb = 8;
        int   src_l = (lane < nb) ? esrc[i + lane] : 0;
        float val_l = (lane < nb) ? eval[i + lane] : 0.f;
        float4 a[8];
#pragma unroll
        for (int j = 0; j < 8; j++) {
            int s0 = __shfl_sync(0xFFFFFFFFu, src_l, j);
            if (j < nb) a[j] = X4[(size_t)s0 * 32 + lane];
        }
#pragma unroll
        for (int j = 0; j < 8; j++) {
            float v0 = __shfl_sync(0xFFFFFFFFu, val_l, j);
            if (j < nb) {
                acc.x += v0 * a[j].x; acc.y += v0 * a[j].y;
                acc.z += v0 * a[j].z; acc.w += v0 * a[j].w;
            }
        }
    }
    acc.x = fmaxf(acc.x, 0.f); acc.y = fmaxf(acc.y, 0.f);
    acc.z = fmaxf(acc.z, 0.f); acc.w = fmaxf(acc.w, 0.f);
    ((float4*)(gcn + (size_t)w * NH))[lane] = acc;
    int d = assign0[w];
    red_add_v4(((float4*)(p1 + (size_t)d * NH)) + lane, acc.x, acc.y, acc.z, acc.w);
}

// ---------------------------------------------------------------------------
// CSR SpMM (40 feats), MLP-8 batched: out = A0 @ X + b2
// ---------------------------------------------------------------------------
__global__ __launch_bounds__(256)
void spmm_csr40(const int* __restrict__ rowptr, const int* __restrict__ esrc,
                const float* __restrict__ eval, const float* __restrict__ X,
                const float* __restrict__ bias, float* __restrict__ out) {
    int w = (blockIdx.x * blockDim.x + threadIdx.x) >> 5;
    int lane = threadIdx.x & 31;
    if (w >= N0) return;
    int s = rowptr[w], e = rowptr[w + 1];
    bool act = lane < 10;
    float4 acc = act ? ((const float4*)bias)[lane] : make_float4(0, 0, 0, 0);
    const float4* X4 = (const float4*)X;

    for (int i = s; i < e; i += 8) {
        int nb = e - i; if (nb > 8) nb = 8;
        int   src_l = (lane < nb) ? esrc[i + lane] : 0;
        float val_l = (lane < nb) ? eval[i + lane] : 0.f;
        float4 a[8];
#pragma unroll
        for (int j = 0; j < 8; j++) {
            int s0 = __shfl_sync(0xFFFFFFFFu, src_l, j);
            if (j < nb && act) a[j] = X4[(size_t)s0 * 10 + lane];
        }
#pragma unroll
        for (int j = 0; j < 8; j++) {
            float v0 = __shfl_sync(0xFFFFFFFFu, val_l, j);
            if (j < nb && act) {
                acc.x += v0 * a[j].x; acc.y += v0 * a[j].y;
                acc.z += v0 * a[j].z; acc.w += v0 * a[j].w;
            }
        }
    }
    if (act) ((float4*)(out + (size_t)w * NC))[lane] = acc;
}

// ---------------------------------------------------------------------------
// Fused CRF: one warp per dst row, online softmax over CSR edges.
// ---------------------------------------------------------------------------
__global__ __launch_bounds__(256)
void crf_fused_k(const int* __restrict__ rowptr, const int* __restrict__ ecol,
                 const float* __restrict__ Q, const float* __restrict__ Km,
                 const float* __restrict__ H0,
                 const float* __restrict__ pa, const float* __restrict__ pb,
                 float* __restrict__ OUT, const int* __restrict__ assign,
                 float* __restrict__ P, int n) {
    int w = (blockIdx.x * blockDim.x + threadIdx.x) >> 5;
    int lane = threadIdx.x & 31;
    if (w >= n) return;
    int s = rowptr[w], e = rowptr[w + 1];
    const float4* K4 = (const float4*)Km;
    const float4* H4 = (const float4*)H0;

    float4 q4 = ((const float4*)(Q + (size_t)w * NH))[lane];

    float m = -3.4e38f, z = 0.f;
    float4 macc = make_float4(0.f, 0.f, 0.f, 0.f);

    for (int i = s; i < e; i += 8) {
        int nb = e - i; if (nb > 8) nb = 8;
        int src_l = (lane < nb) ? ecol[i + lane] : 0;
        float4 buf[8];
#pragma unroll
        for (int j = 0; j < 8; j++) {
            int s0 = __shfl_sync(0xFFFFFFFFu, src_l, j);
            if (j < nb) buf[j] = K4[(size_t)s0 * 32 + lane];
        }
        float lj[8];
#pragma unroll
        for (int j = 0; j < 8; j++) {
            if (j < nb) {
                float d = q4.x * buf[j].x + q4.y * buf[j].y +
                          q4.z * buf[j].z + q4.w * buf[j].w;
#pragma unroll
                for (int o = 16; o; o >>= 1) d += __shfl_xor_sync(0xFFFFFFFFu, d, o);
                lj[j] = d * 0.08838834764831845f;   // 1/sqrt(128)
            }
        }
        float bm = -3.4e38f;
#pragma unroll
        for (int j = 0; j < 8; j++) if (j < nb) bm = fmaxf(bm, lj[j]);
        float nm = fmaxf(m, bm);
        float sc = __expf(m - nm);
        z *= sc;
        macc.x *= sc; macc.y *= sc; macc.z *= sc; macc.w *= sc;
        m = nm;
#pragma unroll
        for (int j = 0; j < 8; j++) {
            int s0 = __shfl_sync(0xFFFFFFFFu, src_l, j);
            if (j < nb) buf[j] = H4[(size_t)s0 * 32 + lane];
        }
#pragma unroll
        for (int j = 0; j < 8; j++) {
            if (j < nb) {
                float ej = __expf(lj[j] - m);
                z += ej;
                macc.x += ej * buf[j].x; macc.y += ej * buf[j].y;
                macc.z += ej * buf[j].z; macc.w += ej * buf[j].w;
            }
        }
    }
    float coef = 1.f / (z + 1e-16f);
    float a = *pa, b = *pb, inv = 1.f / (a + b);
    float4 h0d = H4[(size_t)w * 32 + lane];
    float4 c = make_float4((a * h0d.x + b * macc.x * coef) * inv,
                           (a * h0d.y + b * macc.y * coef) * inv,
                           (a * h0d.z + b * macc.z * coef) * inv,
                           (a * h0d.w + b * macc.w * coef) * inv);
    ((float4*)(OUT + (size_t)w * NH))[lane] = c;
    if (P) {
        int d = assign[w];
        red_add_v4(((float4*)(P + (size_t)d * NH)) + lane, c.x, c.y, c.z, c.w);
    }
}

// ---------------------------------------------------------------------------
// Elementwise kernels
// ---------------------------------------------------------------------------
__global__ void add_emb_k(const float* __restrict__ X, const float* __restrict__ emb,
                          const int* __restrict__ nw, float* __restrict__ H0, int M) {
    int i = blockIdx.x * blockDim.x + threadIdx.x;
    if (i >= M * 32) return;
    int r = i >> 5, c4 = i & 31;
    float4 x = ((const float4*)X)[i];
    float4 e = ((const float4*)(emb + (size_t)nw[r] * NH))[c4];
    ((float4*)H0)[i] = make_float4(x.x + e.x, x.y + e.y, x.z + e.z, x.w + e.w);
}
__global__ void unpool2_k(const float* __restrict__ c2, const float* __restrict__ c1,
                          const float* __restrict__ gcn,
                          const int* __restrict__ assign0, const int* __restrict__ assign1,
                          float* __restrict__ crf) {
    int w = (blockIdx.x * blockDim.x + threadIdx.x) >> 5;
    int lane = threadIdx.x & 31;
    if (w >= N0) return;
    int a0 = assign0[w];
    int a1 = assign1[a0];
    float4 v2 = ((const float4*)(c2 + (size_t)a1 * NH))[lane];
    float4 v1 = ((const float4*)(c1 + (size_t)a0 * NH))[lane];
    float4 vg = ((const float4*)(gcn + (size_t)w * NH))[lane];
    ((float4*)(crf + (size_t)w * NH))[lane] =
        make_float4(v2.x + v1.x + vg.x, v2.y + v1.y + vg.y,
                    v2.z + v1.z + vg.z, v2.w + v1.w + vg.w);
}

// ---------------------------------------------------------------------------
// Host launch
// ---------------------------------------------------------------------------
static inline int cdiv(long long a, long long b) { return (int)((a + b - 1) / b); }

extern "C" void kernel_launch(void* const* d_in, const int* in_sizes, int n_in,
                              void* d_out, int out_size) {
    const float* x       = (const float*)d_in[0];
    const int*   A0      = (const int*)d_in[1];
    const float* A0v     = (const float*)d_in[2];
    const int*   A1      = (const int*)d_in[3];
    const float* A1v     = (const float*)d_in[4];
    const int*   A2      = (const int*)d_in[5];
    const float* A2v     = (const float*)d_in[6];
    const int*   assign0 = (const int*)d_in[7];
    const int*   assign1 = (const int*)d_in[8];
    const int*   nwgt1   = (const int*)d_in[9];
    const int*   nwgt2   = (const int*)d_in[10];
    const float* gc1_W   = (const float*)d_in[11];
    const float* gc1_b   = (const float*)d_in[12];
    const float* gc2_W   = (const float*)d_in[13];
    const float* gc2_b   = (const float*)d_in[14];
    const float* c1Wq    = (const float*)d_in[15];
    const float* c1Wk    = (const float*)d_in[16];
    const float* c1emb   = (const float*)d_in[17];
    const float* c1a     = (const float*)d_in[18];
    const float* c1b     = (const float*)d_in[19];
    const float* c2Wq    = (const float*)d_in[20];
    const float* c2Wk    = (const float*)d_in[21];
    const float* c2emb   = (const float*)d_in[22];
    const float* c2a     = (const float*)d_in[23];
    const float* c2b     = (const float*)d_in[24];

    float* out = (float*)d_out;                       // [N0, NC]
    float* gcn = out + (size_t)N0 * NC;               // [N0, NH]
    float* crf = gcn + (size_t)N0 * NH;               // [N0, NH]

    void *p_xW, *p_p1, *p_q1, *p_k1, *p_h01, *p_c1;
    void *p_p2, *p_q2, *p_k2, *p_h02, *p_c2, *p_hW2, *p_Wtf;
    void *p_cnt, *p_bs, *p_rp, *p_es, *p_ev;
    void *p_rp1, *p_ec1, *p_rp2, *p_ec2;
    cudaGetSymbolAddress(&p_xW, g_xW);   cudaGetSymbolAddress(&p_p1, g_p1);
    cudaGetSymbolAddress(&p_q1, g_q1);   cudaGetSymbolAddress(&p_k1, g_k1);
    cudaGetSymbolAddress(&p_h01, g_h01); cudaGetSymbolAddress(&p_c1, g_c1);
    cudaGetSymbolAddress(&p_p2, g_p2);   cudaGetSymbolAddress(&p_q2, g_q2);
    cudaGetSymbolAddress(&p_k2, g_k2);   cudaGetSymbolAddress(&p_h02, g_h02);
    cudaGetSymbolAddress(&p_c2, g_c2);   cudaGetSymbolAddress(&p_hW2, g_hW2);
    cudaGetSymbolAddress(&p_Wtf, g_Wtf);
    cudaGetSymbolAddress(&p_cnt, g_cntAll); cudaGetSymbolAddress(&p_bs, g_bsum);
    cudaGetSymbolAddress(&p_rp, g_rowptr);
    cudaGetSymbolAddress(&p_es, g_esrc); cudaGetSymbolAddress(&p_ev, g_eval);
    cudaGetSymbolAddress(&p_rp1, g_rowptr1); cudaGetSymbolAddress(&p_ec1, g_ecol1);
    cudaGetSymbolAddress(&p_rp2, g_rowptr2); cudaGetSymbolAddress(&p_ec2, g_ecol2);

    float* xW  = (float*)p_xW;  float* p1 = (float*)p_p1;  float* q1 = (float*)p_q1;
    float* k1  = (float*)p_k1;  float* h01 = (float*)p_h01; float* c1 = (float*)p_c1;
    float* p2  = (float*)p_p2;  float* q2 = (float*)p_q2;  float* k2 = (float*)p_k2;
    float* h02 = (float*)p_h02; float* c2 = (float*)p_c2;  float* hW2 = (float*)p_hW2;
    float* Wtf = (float*)p_Wtf;
    int* cntAll = (int*)p_cnt;  int* bsum = (int*)p_bs;
    int* rowptr = (int*)p_rp;   int* esrc = (int*)p_es;    float* eval = (float*)p_ev;
    int* rowptr1 = (int*)p_rp1; int* ecol1 = (int*)p_ec1;
    int* rowptr2 = (int*)p_rp2; int* ecol2 = (int*)p_ec2;

    const int TB = 256;
    const long long ETOT = (long long)E0 + E1 + E2;
    const int NTOT = N0 + N1 + N2;
    const int IMG = 128 * 128;

    // ---- Prep tf32 weight images ----
    prep_tf32_k<<<cdiv(5 * IMG, TB), TB>>>(gc1_W, c1Wq, c1Wk, c2Wq, c2Wk, Wtf);

    // ---- Fused CSR build for A0/A1/A2 ----
    cudaMemsetAsync(cntAll, 0, (size_t)NTOT * 4);
    hist3_k<<<cdiv(ETOT, TB), TB>>>(A0, A1, A2, cntAll);
    scan1m_k<<<NBLK0 + NBLK1 + NBLK2, 256>>>(cntAll, rowptr, rowptr1, rowptr2, bsum);
    scan2m_k<<<3, 128>>>(bsum);
    scan3m_k<<<cdiv(NTOT, TB), TB>>>(rowptr, rowptr1, rowptr2, bsum);
    scatter3_k<<<cdiv(ETOT, TB), TB>>>(A0, A0v, A1, A2, rowptr, rowptr1, rowptr2,
                                       cntAll, esrc, eval, ecol1, ecol2);

    // ---- GCN layer 1 GEMM (HMMA tf32): xW = x @ W1 ----
    gemm_mma128<<<dim3(cdiv(N0, 128), 1), 256>>>(x, Wtf + 0 * IMG, Wtf + 0 * IMG,
                                                 xW, xW, N0);

    // ---- Fused: gcn = relu(A0 @ xW + b1); p1[assign0] += gcn ----
    cudaMemsetAsync(p1, 0, (size_t)N1 * NH * 4);
    spmm_csr128_fused<<<cdiv((long long)N0 * 32, TB), TB>>>(rowptr, esrc, eval, xW,
                                                            gc1_b, gcn, assign0, p1);

    // ---- level 1 CRF ----
    gemm_mma128<<<dim3(cdiv(N1, 128), 2), 256>>>(p1, Wtf + 1 * IMG, Wtf + 2 * IMG,
                                                 q1, k1, N1);
    add_emb_k<<<cdiv((long long)N1 * 32, TB), TB>>>(p1, c1emb, nwgt1, h01, N1);
    cudaMemsetAsync(p2, 0, (size_t)N2 * NH * 4);
    crf_fused_k<<<cdiv((long long)N1 * 32, TB), TB>>>(rowptr1, ecol1, q1, k1, h01,
                                                      c1a, c1b, c1, assign1, p2, N1);

    // ---- level 2 CRF ----
    gemm_mma128<<<dim3(cdiv(N2, 128), 2), 256>>>(p2, Wtf + 3 * IMG, Wtf + 4 * IMG,
                                                 q2, k2, N2);
    add_emb_k<<<cdiv((long long)N2 * 32, TB), TB>>>(p2, c2emb, nwgt2, h02, N2);
    crf_fused_k<<<cdiv((long long)N2 * 32, TB), TB>>>(rowptr2, ecol2, q2, k2, h02,
                                                      c2a, c2b, c2, nullptr, nullptr, N2);

    // ---- fused unpool with skips ----
    unpool2_k<<<cdiv((long long)N0 * 32, TB), TB>>>(c2, c1, gcn, assign0, assign1, crf);

    // ---- GCN layer 2: out = A0 @ (crf @ W2) + b2 ----
    gemm_n40<<<cdiv(N0, 256), 128>>>(crf, gc2_W, hW2, N0);
    spmm_csr40<<<cdiv((long long)N0 * 32, TB), TB>>>(rowptr, esrc, eval, hW2, gc2_b, out);
}

// round 14
// speedup vs baseline: 1.6179x; 1.0392x over previous
#include <cuda_runtime.h>
#include <cuda_bf16.h>
#include <cstdio>
#include <cstdint>

// Problem constants
#define N0 100000
#define N1 25000
#define N2 6250
#define E0 1600000
#define E1 400000
#define E2 100000
#define NF 128
#define NH 128
#define NC 40
#define NBLK0 98
#define NBLK1 25
#define NBLK2 7

// ---------------------------------------------------------------------------
// Scratch (device globals — no allocation allowed)
// ---------------------------------------------------------------------------
__device__ __align__(16) float g_xW[(size_t)N0 * NH];
__device__ __align__(16) float g_p1[(size_t)N1 * NH];
__device__ __align__(16) float g_q1[(size_t)N1 * NH];
__device__ __align__(16) float g_k1[(size_t)N1 * NH];
__device__ __align__(16) float g_h01[(size_t)N1 * NH];
__device__ __align__(16) float g_c1[(size_t)N1 * NH];
__device__ __align__(16) float g_p2[(size_t)N2 * NH];
__device__ __align__(16) float g_q2[(size_t)N2 * NH];
__device__ __align__(16) float g_k2[(size_t)N2 * NH];
__device__ __align__(16) float g_h02[(size_t)N2 * NH];
__device__ __align__(16) float g_c2[(size_t)N2 * NH];
__device__ __align__(16) float g_hW2[(size_t)N0 * NC];
__device__ __align__(16) float g_Wtf[5 * 128 * 128];    // tf32-converted weights
// CSR scratch (cnt arrays contiguous so one memset clears all three)
__device__ int   g_cntAll[N0 + N1 + N2];
__device__ int   g_bsum[192];
__device__ int   g_rowptr[N0 + 1];
__device__ int   g_esrc[E0];
__device__ float g_eval[E0];
__device__ int   g_rowptr1[N1 + 1];
__device__ int   g_ecol1[E1];
__device__ int   g_rowptr2[N2 + 1];
__device__ int   g_ecol2[E2];

// ---------------------------------------------------------------------------
// Helpers
// ---------------------------------------------------------------------------
__device__ __forceinline__ void red_add_v4(float4* addr, float a, float b, float c, float d) {
    asm volatile("red.global.add.v4.f32 [%0], {%1, %2, %3, %4};"
                 :: "l"(addr), "f"(a), "f"(b), "f"(c), "f"(d) : "memory");
}
__device__ __forceinline__ unsigned long long pack2(float lo, float hi) {
    unsigned long long r;
    asm("mov.b64 %0, {%1, %2};" : "=l"(r) : "f"(lo), "f"(hi));
    return r;
}
__device__ __forceinline__ void fma2(unsigned long long& d, unsigned long long a,
                                     unsigned long long b) {
    asm("fma.rn.f32x2 %0, %1, %2, %0;" : "+l"(d) : "l"(a), "l"(b));
}
__device__ __forceinline__ float2 unpack2(unsigned long long v) {
    float lo, hi;
    asm("mov.b64 {%0, %1}, %2;" : "=f"(lo), "=f"(hi) : "l"(v));
    return make_float2(lo, hi);
}
__device__ __forceinline__ float to_tf32(float x) {
    float r;
    asm("cvt.rna.tf32.f32 %0, %1;" : "=f"(r) : "f"(x));
    return r;
}
#define MMA_TF32(c, a, b)                                                     \
    asm volatile("mma.sync.aligned.m16n8k8.row.col.f32.tf32.tf32.f32 "        \
                 "{%0,%1,%2,%3}, {%4,%5,%6,%7}, {%8,%9}, {%0,%1,%2,%3};"      \
                 : "+f"((c)[0]), "+f"((c)[1]), "+f"((c)[2]), "+f"((c)[3])     \
                 : "r"((a)[0]), "r"((a)[1]), "r"((a)[2]), "r"((a)[3]),        \
                   "r"((b)[0]), "r"((b)[1]))

// ---------------------------------------------------------------------------
// Prep: convert 5 weight matrices [128,128] to tf32 (rna) once.
// ---------------------------------------------------------------------------
__global__ void prep_tf32_k(const float* __restrict__ w0, const float* __restrict__ w1,
                            const float* __restrict__ w2, const float* __restrict__ w3,
                            const float* __restrict__ w4, float* __restrict__ out) {
    int t = blockIdx.x * blockDim.x + threadIdx.x;   // 0 .. 5*16384-1
    if (t >= 5 * 16384) return;
    int sel = t >> 14, i = t & 16383;
    const float* w = (sel == 0) ? w0 : (sel == 1) ? w1 : (sel == 2) ? w2
                                     : (sel == 3) ? w3 : w4;
    out[t] = to_tf32(w[i]);
}

// ---------------------------------------------------------------------------
// Fused CSR build for all three graphs
// ---------------------------------------------------------------------------
__global__ void hist3_k(const int* __restrict__ A0, const int* __restrict__ A1,
                        const int* __restrict__ A2, int* __restrict__ cntAll) {
    int t = blockIdx.x * blockDim.x + threadIdx.x;
    if (t < E0) atomicAdd(cntAll + A0[t], 1);
    else if (t < E0 + E1) atomicAdd(cntAll + N0 + A1[t - E0], 1);
    else if (t < E0 + E1 + E2) atomicAdd(cntAll + N0 + N1 + A2[t - E0 - E1], 1);
}
__global__ void scan1m_k(const int* __restrict__ cntAll, int* __restrict__ rp0,
                         int* __restrict__ rp1, int* __restrict__ rp2,
                         int* __restrict__ bsum) {
    __shared__ int s[256];
    int b = blockIdx.x, t = threadIdx.x;
    const int* cnt; int* rowptr; int n, lb;
    if (b < NBLK0)              { cnt = cntAll;            rowptr = rp0; n = N0; lb = b; }
    else if (b < NBLK0 + NBLK1) { cnt = cntAll + N0;       rowptr = rp1; n = N1; lb = b - NBLK0; }
    else                        { cnt = cntAll + N0 + N1;  rowptr = rp2; n = N2; lb = b - NBLK0 - NBLK1; }
    int base = lb * 1024 + t * 4;
    int v0 = (base + 0 < n) ? cnt[base + 0] : 0;
    int v1 = (base + 1 < n) ? cnt[base + 1] : 0;
    int v2 = (base + 2 < n) ? cnt[base + 2] : 0;
    int v3 = (base + 3 < n) ? cnt[base + 3] : 0;
    int x0 = v0, x1 = x0 + v1, x2 = x1 + v2, x3 = x2 + v3;
    s[t] = x3;
    __syncthreads();
    for (int off = 1; off < 256; off <<= 1) {
        int val = 0;
        if (t >= off) val = s[t - off];
        __syncthreads();
        if (t >= off) s[t] += val;
        __syncthreads();
    }
    int prev = (t > 0) ? s[t - 1] : 0;
    if (base + 0 < n) rowptr[base + 1] = prev + x0;
    if (base + 1 < n) rowptr[base + 2] = prev + x1;
    if (base + 2 < n) rowptr[base + 3] = prev + x2;
    if (base + 3 < n) rowptr[base + 4] = prev + x3;
    if (t == 255) bsum[b] = s[255];
}
__global__ void scan2m_k(int* __restrict__ bsum) {
    __shared__ int s[128];
    int g = blockIdx.x, t = threadIdx.x;
    int base = (g == 0) ? 0 : ((g == 1) ? NBLK0 : NBLK0 + NBLK1);
    int nb   = (g == 0) ? NBLK0 : ((g == 1) ? NBLK1 : NBLK2);
    int v = (t < nb) ? bsum[base + t] : 0;
    s[t] = v;
    __syncthreads();
    for (int off = 1; off < 128; off <<= 1) {
        int val = 0;
        if (t >= off) val = s[t - off];
        __syncthreads();
        if (t >= off) s[t] += val;
        __syncthreads();
    }
    if (t < nb) bsum[base + t] = s[t] - v;   // exclusive
}
__global__ void scan3m_k(int* __restrict__ rp0, int* __restrict__ rp1,
                         int* __restrict__ rp2, const int* __restrict__ bsum) {
    int i = blockIdx.x * blockDim.x + threadIdx.x;
    if (i < N0) {
        if (i == 0) rp0[0] = 0;
        rp0[i + 1] += bsum[i >> 10];
    } else if (i < N0 + N1) {
        int j = i - N0;
        if (j == 0) rp1[0] = 0;
        rp1[j + 1] += bsum[NBLK0 + (j >> 10)];
    } else if (i < N0 + N1 + N2) {
        int j = i - N0 - N1;
        if (j == 0) rp2[0] = 0;
        rp2[j + 1] += bsum[NBLK0 + NBLK1 + (j >> 10)];
    }
}
// Reverse-fill scatter: consumes leftover histogram via atomicSub (no cursor memset).
__global__ void scatter3_k(const int* __restrict__ A0, const float* __restrict__ A0v,
                           const int* __restrict__ A1, const int* __restrict__ A2,
                           const int* __restrict__ rp0, const int* __restrict__ rp1,
                           const int* __restrict__ rp2, int* __restrict__ cntAll,
                           int* __restrict__ esrc, float* __restrict__ eval,
                           int* __restrict__ ecol1, int* __restrict__ ecol2) {
    int t = blockIdx.x * blockDim.x + threadIdx.x;
    if (t < E0) {
        int d = A0[t];
        int old = atomicSub(cntAll + d, 1);
        int pos = rp0[d] + old - 1;
        esrc[pos] = A0[E0 + t];
        eval[pos] = A0v[t];
    } else if (t < E0 + E1) {
        int e = t - E0;
        int d = A1[e];
        int old = atomicSub(cntAll + N0 + d, 1);
        ecol1[rp1[d] + old - 1] = A1[E1 + e];
    } else if (t < E0 + E1 + E2) {
        int e = t - E0 - E1;
        int d = A2[e];
        int old = atomicSub(cntAll + N0 + N1 + d, 1);
        ecol2[rp2[d] + old - 1] = A2[E2 + e];
    }
}

// ---------------------------------------------------------------------------
// HMMA tf32 GEMM: C[M,128] = A[M,128] @ W[128,128]   (W pre-converted tf32)
// ---------------------------------------------------------------------------
__global__ __launch_bounds__(256, 2)
void gemm_mma128(const float* __restrict__ A,
                 const float* __restrict__ B0w, const float* __restrict__ B1w,
                 float* __restrict__ C0, float* __restrict__ C1, int M) {
    __shared__ __align__(16) float As[128][20];
    __shared__ __align__(16) float Bs[16][136];
    const float* __restrict__ B = blockIdx.y ? B1w : B0w;
    float* __restrict__ C = blockIdx.y ? C1 : C0;

    int tid = threadIdx.x;
    int wid = tid >> 5, lane = tid & 31;
    int wm = wid >> 2;
    int wn = wid & 3;
    int g = lane >> 2;
    int a4 = lane & 3;
    int row0 = blockIdx.x * 128;

    float acc[4][4][4] = {};

    for (int st = 0; st < 8; st++) {
        int k0 = st * 16;
#pragma unroll
        for (int it = 0; it < 2; it++) {
            int idx = tid + it * 256;
            int m = idx >> 2, q = idx & 3;
            float4 v = make_float4(0.f, 0.f, 0.f, 0.f);
            if (row0 + m < M)
                v = *(const float4*)(A + (size_t)(row0 + m) * 128 + k0 + q * 4);
            v.x = to_tf32(v.x); v.y = to_tf32(v.y);
            v.z = to_tf32(v.z); v.w = to_tf32(v.w);
            *(float4*)&As[m][q * 4] = v;
        }
#pragma unroll
        for (int it = 0; it < 2; it++) {
            int idx = tid + it * 256;
            int k = idx >> 5, c = idx & 31;
            *(float4*)&Bs[k][c * 4] = *(const float4*)(B + (size_t)(k0 + k) * 128 + c * 4);
        }
        __syncthreads();
#pragma unroll
        for (int kl0 = 0; kl0 < 16; kl0 += 8) {
            int kc = kl0 + a4;
            uint32_t af[4][4];
#pragma unroll
            for (int i = 0; i < 4; i++) {
                int r = wm * 64 + i * 16 + g;
                af[i][0] = __float_as_uint(As[r][kc]);
                af[i][1] = __float_as_uint(As[r + 8][kc]);
                af[i][2] = __float_as_uint(As[r][kc + 4]);
                af[i][3] = __float_as_uint(As[r + 8][kc + 4]);
            }
            uint32_t bf[4][2];
#pragma unroll
            for (int j = 0; j < 4; j++) {
                int n = wn * 32 + j * 8 + g;
                bf[j][0] = __float_as_uint(Bs[kc][n]);
                bf[j][1] = __float_as_uint(Bs[kc + 4][n]);
            }
#pragma unroll
            for (int i = 0; i < 4; i++)
#pragma unroll
                for (int j = 0; j < 4; j++)
                    MMA_TF32(acc[i][j], af[i], bf[j]);
        }
        __syncthreads();
    }
#pragma unroll
    for (int i = 0; i < 4; i++) {
        int r = row0 + wm * 64 + i * 16 + g;
#pragma unroll
        for (int j = 0; j < 4; j++) {
            int cn = wn * 32 + j * 8 + 2 * a4;
            if (r < M)
                *(float2*)(C + (size_t)r * 128 + cn) = make_float2(acc[i][j][0], acc[i][j][1]);
            if (r + 8 < M)
                *(float2*)(C + (size_t)(r + 8) * 128 + cn) = make_float2(acc[i][j][2], acc[i][j][3]);
        }
    }
}

// ---------------------------------------------------------------------------
// GEMM C[M,40] = A[M,128] @ W[128,40], packed f32x2, 2 rows per thread.
// ---------------------------------------------------------------------------
__global__ __launch_bounds__(128)
void gemm_n40(const float* __restrict__ A, const float* __restrict__ W,
              float* __restrict__ C, int M) {
    __shared__ unsigned long long Ws2[128][20];
    int tid = threadIdx.x;
    for (int i = tid; i < 128 * 20; i += 128) {
        int k = i / 20, p = i % 20;
        Ws2[k][p] = pack2(W[k * 40 + 2 * p], W[k * 40 + 2 * p + 1]);
    }
    __syncthreads();
    int row0 = blockIdx.x * 256 + tid;
    int row1 = row0 + 128;
    bool ok0 = row0 < M, ok1 = row1 < M;
    if (!ok0) return;
    const float4* a4_0 = (const float4*)(A + (size_t)row0 * 128);
    const float4* a4_1 = (const float4*)(A + (size_t)row1 * 128);
    unsigned long long acc0[20] = {}, acc1[20] = {};
    for (int kq = 0; kq < 32; kq++) {
        float4 va = a4_0[kq];
        float4 vb = ok1 ? a4_1[kq] : make_float4(0, 0, 0, 0);
        float av[4] = {va.x, va.y, va.z, va.w};
        float bv[4] = {vb.x, vb.y, vb.z, vb.w};
#pragma unroll
        for (int j = 0; j < 4; j++) {
            unsigned long long a0d = pack2(av[j], av[j]);
            unsigned long long a1d = pack2(bv[j], bv[j]);
            const unsigned long long* wr = &Ws2[kq * 4 + j][0];
#pragma unroll
            for (int p = 0; p < 20; p++) {
                unsigned long long w = wr[p];
                fma2(acc0[p], a0d, w);
                fma2(acc1[p], a1d, w);
            }
        }
    }
    float* cp0 = C + (size_t)row0 * 40;
#pragma unroll
    for (int p = 0; p < 10; p++) {
        float2 lo = unpack2(acc0[2 * p]), hi = unpack2(acc0[2 * p + 1]);
        *(float4*)(cp0 + 4 * p) = make_float4(lo.x, lo.y, hi.x, hi.y);
    }
    if (ok1) {
        float* cp1 = C + (size_t)row1 * 40;
#pragma unroll
        for (int p = 0; p < 10; p++) {
            float2 lo = unpack2(acc1[2 * p]), hi = unpack2(acc1[2 * p + 1]);
            *(float4*)(cp1 + 4 * p) = make_float4(lo.x, lo.y, hi.x, hi.y);
        }
    }
}

// ---------------------------------------------------------------------------
// CSR SpMM (128 feats) fused, MLP-8 batched gathers:
// gcn = relu(A0 @ X + b); p1[assign0] += gcn
// ---------------------------------------------------------------------------
__global__ __launch_bounds__(256)
void spmm_csr128_fused(const int* __restrict__ rowptr, const int* __restrict__ esrc,
                       const float* __restrict__ eval, const float* __restrict__ X,
                       const float* __restrict__ bias, float* __restrict__ gcn,
                       const int* __restrict__ assign0, float* __restrict__ p1) {
    int w = (blockIdx.x * blockDim.x + threadIdx.x) >> 5;
    int lane = threadIdx.x & 31;
    if (w >= N0) return;
    int s = rowptr[w], e = rowptr[w + 1];
    float4 acc = ((const float4*)bias)[lane];
    const float4* X4 = (const float4*)X;

    for (int i = s; i < e; i += 8) {
        int nb = e - i; if (nb > 8) nb = 8;
        int   src_l = (lane < nb) ? esrc[i + lane] : 0;
        float val_l = (lane < nb) ? eval[i + lane] : 0.f;
        float4 a[8];
#pragma unroll
        for (int j = 0; j < 8; j++) {
            int s0 = __shfl_sync(0xFFFFFFFFu, src_l, j);
            if (j < nb) a[j] = X4[(size_t)s0 * 32 + lane];
        }
#pragma unroll
        for (int j = 0; j < 8; j++) {
            float v0 = __shfl_sync(0xFFFFFFFFu, val_l, j);
            if (j < nb) {
                acc.x += v0 * a[j].x; acc.y += v0 * a[j].y;
                acc.z += v0 * a[j].z; acc.w += v0 * a[j].w;
            }
        }
    }
    acc.x = fmaxf(acc.x, 0.f); acc.y = fmaxf(acc.y, 0.f);
    acc.z = fmaxf(acc.z, 0.f); acc.w = fmaxf(acc.w, 0.f);
    ((float4*)(gcn + (size_t)w * NH))[lane] = acc;
    int d = assign0[w];
    red_add_v4(((float4*)(p1 + (size_t)d * NH)) + lane, acc.x, acc.y, acc.z, acc.w);
}

// ---------------------------------------------------------------------------
// CSR SpMM (40 feats), MLP-8 batched: out = A0 @ X + b2
// ---------------------------------------------------------------------------
__global__ __launch_bounds__(256)
void spmm_csr40(const int* __restrict__ rowptr, const int* __restrict__ esrc,
                const float* __restrict__ eval, const float* __restrict__ X,
                const float* __restrict__ bias, float* __restrict__ out) {
    int w = (blockIdx.x * blockDim.x + threadIdx.x) >> 5;
    int lane = threadIdx.x & 31;
    if (w >= N0) return;
    int s = rowptr[w], e = rowptr[w + 1];
    bool act = lane < 10;
    float4 acc = act ? ((const float4*)bias)[lane] : make_float4(0, 0, 0, 0);
    const float4* X4 = (const float4*)X;

    for (int i = s; i < e; i += 8) {
        int nb = e - i; if (nb > 8) nb = 8;
        int   src_l = (lane < nb) ? esrc[i + lane] : 0;
        float val_l = (lane < nb) ? eval[i + lane] : 0.f;
        float4 a[8];
#pragma unroll
        for (int j = 0; j < 8; j++) {
            int s0 = __shfl_sync(0xFFFFFFFFu, src_l, j);
            if (j < nb && act) a[j] = X4[(size_t)s0 * 10 + lane];
        }
#pragma unroll
        for (int j = 0; j < 8; j++) {
            float v0 = __shfl_sync(0xFFFFFFFFu, val_l, j);
            if (j < nb && act) {
                acc.x += v0 * a[j].x; acc.y += v0 * a[j].y;
                acc.z += v0 * a[j].z; acc.w += v0 * a[j].w;
            }
        }
    }
    if (act) ((float4*)(out + (size_t)w * NC))[lane] = acc;
}

// ---------------------------------------------------------------------------
// Fused CRF: one warp per dst row, online softmax over CSR edges.
// ---------------------------------------------------------------------------
__global__ __launch_bounds__(256)
void crf_fused_k(const int* __restrict__ rowptr, const int* __restrict__ ecol,
                 const float* __restrict__ Q, const float* __restrict__ Km,
                 const float* __restrict__ H0,
                 const float* __restrict__ pa, const float* __restrict__ pb,
                 float* __restrict__ OUT, const int* __restrict__ assign,
                 float* __restrict__ P, int n) {
    int w = (blockIdx.x * blockDim.x + threadIdx.x) >> 5;
    int lane = threadIdx.x & 31;
    if (w >= n) return;
    int s = rowptr[w], e = rowptr[w + 1];
    const float4* K4 = (const float4*)Km;
    const float4* H4 = (const float4*)H0;

    float4 q4 = ((const float4*)(Q + (size_t)w * NH))[lane];

    float m = -3.4e38f, z = 0.f;
    float4 macc = make_float4(0.f, 0.f, 0.f, 0.f);

    for (int i = s; i < e; i += 8) {
        int nb = e - i; if (nb > 8) nb = 8;
        int src_l = (lane < nb) ? ecol[i + lane] : 0;
        float4 buf[8];
#pragma unroll
        for (int j = 0; j < 8; j++) {
            int s0 = __shfl_sync(0xFFFFFFFFu, src_l, j);
            if (j < nb) buf[j] = K4[(size_t)s0 * 32 + lane];
        }
        float lj[8];
#pragma unroll
        for (int j = 0; j < 8; j++) {
            if (j < nb) {
                float d = q4.x * buf[j].x + q4.y * buf[j].y +
                          q4.z * buf[j].z + q4.w * buf[j].w;
#pragma unroll
                for (int o = 16; o; o >>= 1) d += __shfl_xor_sync(0xFFFFFFFFu, d, o);
                lj[j] = d * 0.08838834764831845f;   // 1/sqrt(128)
            }
        }
        float bm = -3.4e38f;
#pragma unroll
        for (int j = 0; j < 8; j++) if (j < nb) bm = fmaxf(bm, lj[j]);
        float nm = fmaxf(m, bm);
        float sc = __expf(m - nm);
        z *= sc;
        macc.x *= sc; macc.y *= sc; macc.z *= sc; macc.w *= sc;
        m = nm;
#pragma unroll
        for (int j = 0; j < 8; j++) {
            int s0 = __shfl_sync(0xFFFFFFFFu, src_l, j);
            if (j < nb) buf[j] = H4[(size_t)s0 * 32 + lane];
        }
#pragma unroll
        for (int j = 0; j < 8; j++) {
            if (j < nb) {
                float ej = __expf(lj[j] - m);
                z += ej;
                macc.x += ej * buf[j].x; macc.y += ej * buf[j].y;
                macc.z += ej * buf[j].z; macc.w += ej * buf[j].w;
            }
        }
    }
    float coef = 1.f / (z + 1e-16f);
    float a = *pa, b = *pb, inv = 1.f / (a + b);
    float4 h0d = H4[(size_t)w * 32 + lane];
    float4 c = make_float4((a * h0d.x + b * macc.x * coef) * inv,
                           (a * h0d.y + b * macc.y * coef) * inv,
                           (a * h0d.z + b * macc.z * coef) * inv,
                           (a * h0d.w + b * macc.w * coef) * inv);
    ((float4*)(OUT + (size_t)w * NH))[lane] = c;
    if (P) {
        int d = assign[w];
        red_add_v4(((float4*)(P + (size_t)d * NH)) + lane, c.x, c.y, c.z, c.w);
    }
}

// ---------------------------------------------------------------------------
// Elementwise kernels
// ---------------------------------------------------------------------------
__global__ void add_emb_k(const float* __restrict__ X, const float* __restrict__ emb,
                          const int* __restrict__ nw, float* __restrict__ H0, int M) {
    int i = blockIdx.x * blockDim.x + threadIdx.x;
    if (i >= M * 32) return;
    int r = i >> 5, c4 = i & 31;
    float4 x = ((const float4*)X)[i];
    float4 e = ((const float4*)(emb + (size_t)nw[r] * NH))[c4];
    ((float4*)H0)[i] = make_float4(x.x + e.x, x.y + e.y, x.z + e.z, x.w + e.w);
}
__global__ void unpool2_k(const float* __restrict__ c2, const float* __restrict__ c1,
                          const float* __restrict__ gcn,
                          const int* __restrict__ assign0, const int* __restrict__ assign1,
                          float* __restrict__ crf) {
    int w = (blockIdx.x * blockDim.x + threadIdx.x) >> 5;
    int lane = threadIdx.x & 31;
    if (w >= N0) return;
    int a0 = assign0[w];
    int a1 = assign1[a0];
    float4 v2 = ((const float4*)(c2 + (size_t)a1 * NH))[lane];
    float4 v1 = ((const float4*)(c1 + (size_t)a0 * NH))[lane];
    float4 vg = ((const float4*)(gcn + (size_t)w * NH))[lane];
    ((float4*)(crf + (size_t)w * NH))[lane] =
        make_float4(v2.x + v1.x + vg.x, v2.y + v1.y + vg.y,
                    v2.z + v1.z + vg.z, v2.w + v1.w + vg.w);
}

// ---------------------------------------------------------------------------
// Host launch
// ---------------------------------------------------------------------------
static inline int cdiv(long long a, long long b) { return (int)((a + b - 1) / b); }

extern "C" void kernel_launch(void* const* d_in, const int* in_sizes, int n_in,
                              void* d_out, int out_size) {
    const float* x       = (const float*)d_in[0];
    const int*   A0      = (const int*)d_in[1];
    const float* A0v     = (const float*)d_in[2];
    const int*   A1      = (const int*)d_in[3];
    const float* A1v     = (const float*)d_in[4];
    const int*   A2      = (const int*)d_in[5];
    const float* A2v     = (const float*)d_in[6];
    const int*   assign0 = (const int*)d_in[7];
    const int*   assign1 = (const int*)d_in[8];
    const int*   nwgt1   = (const int*)d_in[9];
    const int*   nwgt2   = (const int*)d_in[10];
    const float* gc1_W   = (const float*)d_in[11];
    const float* gc1_b   = (const float*)d_in[12];
    const float* gc2_W   = (const float*)d_in[13];
    const float* gc2_b   = (const float*)d_in[14];
    const float* c1Wq    = (const float*)d_in[15];
    const float* c1Wk    = (const float*)d_in[16];
    const float* c1emb   = (const float*)d_in[17];
    const float* c1a     = (const float*)d_in[18];
    const float* c1b     = (const float*)d_in[19];
    const float* c2Wq    = (const float*)d_in[20];
    const float* c2Wk    = (const float*)d_in[21];
    const float* c2emb   = (const float*)d_in[22];
    const float* c2a     = (const float*)d_in[23];
    const float* c2b     = (const float*)d_in[24];

    float* out = (float*)d_out;                       // [N0, NC]
    float* gcn = out + (size_t)N0 * NC;               // [N0, NH]
    float* crf = gcn + (size_t)N0 * NH;               // [N0, NH]

    void *p_xW, *p_p1, *p_q1, *p_k1, *p_h01, *p_c1;
    void *p_p2, *p_q2, *p_k2, *p_h02, *p_c2, *p_hW2, *p_Wtf;
    void *p_cnt, *p_bs, *p_rp, *p_es, *p_ev;
    void *p_rp1, *p_ec1, *p_rp2, *p_ec2;
    cudaGetSymbolAddress(&p_xW, g_xW);   cudaGetSymbolAddress(&p_p1, g_p1);
    cudaGetSymbolAddress(&p_q1, g_q1);   cudaGetSymbolAddress(&p_k1, g_k1);
    cudaGetSymbolAddress(&p_h01, g_h01); cudaGetSymbolAddress(&p_c1, g_c1);
    cudaGetSymbolAddress(&p_p2, g_p2);   cudaGetSymbolAddress(&p_q2, g_q2);
    cudaGetSymbolAddress(&p_k2, g_k2);   cudaGetSymbolAddress(&p_h02, g_h02);
    cudaGetSymbolAddress(&p_c2, g_c2);   cudaGetSymbolAddress(&p_hW2, g_hW2);
    cudaGetSymbolAddress(&p_Wtf, g_Wtf);
    cudaGetSymbolAddress(&p_cnt, g_cntAll); cudaGetSymbolAddress(&p_bs, g_bsum);
    cudaGetSymbolAddress(&p_rp, g_rowptr);
    cudaGetSymbolAddress(&p_es, g_esrc); cudaGetSymbolAddress(&p_ev, g_eval);
    cudaGetSymbolAddress(&p_rp1, g_rowptr1); cudaGetSymbolAddress(&p_ec1, g_ecol1);
    cudaGetSymbolAddress(&p_rp2, g_rowptr2); cudaGetSymbolAddress(&p_ec2, g_ecol2);

    float* xW  = (float*)p_xW;  float* p1 = (float*)p_p1;  float* q1 = (float*)p_q1;
    float* k1  = (float*)p_k1;  float* h01 = (float*)p_h01; float* c1 = (float*)p_c1;
    float* p2  = (float*)p_p2;  float* q2 = (float*)p_q2;  float* k2 = (float*)p_k2;
    float* h02 = (float*)p_h02; float* c2 = (float*)p_c2;  float* hW2 = (float*)p_hW2;
    float* Wtf = (float*)p_Wtf;
    int* cntAll = (int*)p_cnt;  int* bsum = (int*)p_bs;
    int* rowptr = (int*)p_rp;   int* esrc = (int*)p_es;    float* eval = (float*)p_ev;
    int* rowptr1 = (int*)p_rp1; int* ecol1 = (int*)p_ec1;
    int* rowptr2 = (int*)p_rp2; int* ecol2 = (int*)p_ec2;

    const int TB = 256;
    const long long ETOT = (long long)E0 + E1 + E2;
    const int NTOT = N0 + N1 + N2;
    const int IMG = 128 * 128;

    // One-time side stream + events (created on the first, non-capture call).
    static cudaStream_t s1 = nullptr;
    static cudaEvent_t evFork = nullptr, evJoin = nullptr;
    if (!s1) {
        cudaStreamCreateWithFlags(&s1, cudaStreamNonBlocking);
        cudaEventCreateWithFlags(&evFork, cudaEventDisableTiming);
        cudaEventCreateWithFlags(&evJoin, cudaEventDisableTiming);
    }

    // ---- Fork: side stream builds the CSRs + clears pool buffers ----
    cudaEventRecord(evFork, 0);
    cudaStreamWaitEvent(s1, evFork, 0);

    cudaMemsetAsync(cntAll, 0, (size_t)NTOT * 4, s1);
    cudaMemsetAsync(p1, 0, (size_t)N1 * NH * 4, s1);
    cudaMemsetAsync(p2, 0, (size_t)N2 * NH * 4, s1);
    hist3_k<<<cdiv(ETOT, TB), TB, 0, s1>>>(A0, A1, A2, cntAll);
    scan1m_k<<<NBLK0 + NBLK1 + NBLK2, 256, 0, s1>>>(cntAll, rowptr, rowptr1, rowptr2, bsum);
    scan2m_k<<<3, 128, 0, s1>>>(bsum);
    scan3m_k<<<cdiv(NTOT, TB), TB, 0, s1>>>(rowptr, rowptr1, rowptr2, bsum);
    scatter3_k<<<cdiv(ETOT, TB), TB, 0, s1>>>(A0, A0v, A1, A2, rowptr, rowptr1, rowptr2,
                                              cntAll, esrc, eval, ecol1, ecol2);
    cudaEventRecord(evJoin, s1);

    // ---- Main stream: dense front-end (independent of CSR) ----
    prep_tf32_k<<<cdiv(5 * IMG, TB), TB>>>(gc1_W, c1Wq, c1Wk, c2Wq, c2Wk, Wtf);
    gemm_mma128<<<dim3(cdiv(N0, 128), 1), 256>>>(x, Wtf + 0 * IMG, Wtf + 0 * IMG,
                                                 xW, xW, N0);

    // ---- Join: everything below needs both chains ----
    cudaStreamWaitEvent(0, evJoin, 0);

    // ---- Fused: gcn = relu(A0 @ xW + b1); p1[assign0] += gcn ----
    spmm_csr128_fused<<<cdiv((long long)N0 * 32, TB), TB>>>(rowptr, esrc, eval, xW,
                                                            gc1_b, gcn, assign0, p1);

    // ---- level 1 CRF ----
    gemm_mma128<<<dim3(cdiv(N1, 128), 2), 256>>>(p1, Wtf + 1 * IMG, Wtf + 2 * IMG,
                                                 q1, k1, N1);
    add_emb_k<<<cdiv((long long)N1 * 32, TB), TB>>>(p1, c1emb, nwgt1, h01, N1);
    crf_fused_k<<<cdiv((long long)N1 * 32, TB), TB>>>(rowptr1, ecol1, q1, k1, h01,
                                                      c1a, c1b, c1, assign1, p2, N1);

    // ---- level 2 CRF ----
    gemm_mma128<<<dim3(cdiv(N2, 128), 2), 256>>>(p2, Wtf + 3 * IMG, Wtf + 4 * IMG,
                                                 q2, k2, N2);
    add_emb_k<<<cdiv((long long)N2 * 32, TB), TB>>>(p2, c2emb, nwgt2, h02, N2);
    crf_fused_k<<<cdiv((long long)N2 * 32, TB), TB>>>(rowptr2, ecol2, q2, k2, h02,
                                                      c2a, c2b, c2, nullptr, nullptr, N2);

    // ---- fused unpool with skips ----
    unpool2_k<<<cdiv((long long)N0 * 32, TB), TB>>>(c2, c1, gcn, assign0, assign1, crf);

    // ---- GCN layer 2: out = A0 @ (crf @ W2) + b2 ----
    gemm_n40<<<cdiv(N0, 256), 128>>>(crf, gc2_W, hW2, N0);
    spmm_csr40<<<cdiv((long long)N0 * 32, TB), TB>>>(rowptr, esrc, eval, hW2, gc2_b, out);
}